// round 14
// baseline (speedup 1.0000x reference)
#include <cuda_runtime.h>
#include <cuda_fp16.h>
#include <math.h>
#include <stdint.h>

// ---------------------------------------------------------------------------
// PTransformerBlock: S=2048 B=4 D=1024 H=16 K=64 FF=4096.
// Round 14: GEMM with 64x64 warp tiles at 2 CTAs/SM (128-thread CTAs,
//           halves smem crossbar traffic per FLOP). FA2 attention unchanged.
// ---------------------------------------------------------------------------

#define SEQ   2048
#define BATCH 4
#define DMODEL 1024
#define FFDIM 4096
#define MROWS (SEQ*BATCH)   // 8192
#define LN_EPS 1e-5f

// scratch (allocation-free: device globals)
__device__ __half g_xh  [MROWS * DMODEL];
__device__ __half g_wph [3072 * DMODEL];
__device__ __half g_wch [DMODEL * DMODEL];
__device__ __half g_w1h [FFDIM * DMODEL];
__device__ __half g_w2h [DMODEL * FFDIM];
__device__ __half g_qkvh[MROWS * 3072];
__device__ __half g_uh  [MROWS * DMODEL];
__device__ __half g_t2h [MROWS * DMODEL];
__device__ __half g_hidh[MROWS * FFDIM];
__device__ float  g_t1  [MROWS * DMODEL];
__device__ float  g_t2  [MROWS * DMODEL];
__device__ float  g_t3  [MROWS * DMODEL];

__device__ __forceinline__ uint32_t h2u(__half2 h) {
    union { __half2 h; uint32_t u; } c;
    c.h = h;
    return c.u;
}

__device__ __forceinline__ void mma_f16(
    float& d0, float& d1, float& d2, float& d3,
    uint32_t a0, uint32_t a1, uint32_t a2, uint32_t a3,
    uint32_t b0, uint32_t b1)
{
    asm volatile(
        "mma.sync.aligned.m16n8k16.row.col.f32.f16.f16.f32 "
        "{%0,%1,%2,%3}, {%4,%5,%6,%7}, {%8,%9}, {%0,%1,%2,%3};"
        : "+f"(d0), "+f"(d1), "+f"(d2), "+f"(d3)
        : "r"(a0), "r"(a1), "r"(a2), "r"(a3), "r"(b0), "r"(b1));
}

__device__ __forceinline__ void ldsm4(
    uint32_t& r0, uint32_t& r1, uint32_t& r2, uint32_t& r3, uint32_t addr)
{
    asm volatile("ldmatrix.sync.aligned.m8n8.x4.shared.b16 {%0,%1,%2,%3}, [%4];"
                 : "=r"(r0), "=r"(r1), "=r"(r2), "=r"(r3) : "r"(addr));
}
__device__ __forceinline__ void ldsm4_t(
    uint32_t& r0, uint32_t& r1, uint32_t& r2, uint32_t& r3, uint32_t addr)
{
    asm volatile("ldmatrix.sync.aligned.m8n8.x4.trans.shared.b16 {%0,%1,%2,%3}, [%4];"
                 : "=r"(r0), "=r"(r1), "=r"(r2), "=r"(r3) : "r"(addr));
}

__device__ __forceinline__ void cp16(uint32_t s, const void* g) {
    asm volatile("cp.async.cg.shared.global [%0], [%1], 16;" :: "r"(s), "l"(g));
}
__device__ __forceinline__ uint32_t saddr(const void* p) {
    return (uint32_t)__cvta_generic_to_shared(p);
}
#define SWZ128(o) ((o) ^ (((o) >> 3) & 0x70))

// ---------------------------------------------------------------------------
// fp16 tensor-core GEMM: C[M,N] = A[M,Kd] * W[N,Kd]^T (+ epilogue)
// CTA 128x128, BK=64, **128 threads = 4 warps of 64x64** (2x2 warp grid).
// 2 CTAs/SM: smem read traffic per SM per k-tile = 128KB (vs 192KB before).
// 3-stage cp.async, one __syncthreads per k-tile.
// EPI: 0=none,fp16  1=+bias,relu,fp16  2=+bias,+res,f32  3=+res,f32
// ---------------------------------------------------------------------------
#define STAGE_BYTES 32768
#define NSTAGE 3
#define GEMM_SMEM_BYTES (NSTAGE * STAGE_BYTES)

__device__ __forceinline__ void load_tile_h(
    uint32_t base, const __half* __restrict__ A, const __half* __restrict__ W,
    int m0, int n0, int Kd, int k0, int tid)
{
#pragma unroll
    for (int it = 0; it < 8; it++) {       // 1024 chunks each for A and B
        int lin = tid + it * 128;
        int row = lin >> 3;
        int ch  = lin & 7;
        uint32_t off = (uint32_t)(row * 128 + ch * 16);
        uint32_t sw  = SWZ128(off);
        cp16(base + sw,         A + (size_t)(m0 + row) * Kd + k0 + ch * 8);
        cp16(base + 16384 + sw, W + (size_t)(n0 + row) * Kd + k0 + ch * 8);
    }
}

__global__ __launch_bounds__(128, 2) void gemm_h(
    const __half* __restrict__ A, const __half* __restrict__ W,
    const float* __restrict__ bias, const float* __restrict__ res,
    void* __restrict__ Cv, int N, int Kd, int EPI)
{
    extern __shared__ __align__(1024) char smem[];

    const int tid  = threadIdx.x;
    const int warp = tid >> 5;
    const int lane = tid & 31;
    const int gr   = lane >> 2;
    const int tig  = lane & 3;
    const int wm   = (warp & 1) * 64;     // 2 M-slots
    const int wn   = (warp >> 1) * 64;    // 2 N-slots
    const int m0   = blockIdx.y * 128;
    const int n0   = blockIdx.x * 128;

    const uint32_t sb = saddr(smem);

    float acc[4][8][4];
#pragma unroll
    for (int mt = 0; mt < 4; mt++)
#pragma unroll
        for (int nt = 0; nt < 8; nt++)
#pragma unroll
            for (int c = 0; c < 4; c++) acc[mt][nt][c] = 0.f;

    const int ktiles = Kd >> 6;

    // prologue: prefetch tiles 0 and 1
#pragma unroll
    for (int pf = 0; pf < 2; pf++) {
        load_tile_h(sb + pf * STAGE_BYTES, A, W, m0, n0, Kd, pf * 64, tid);
        asm volatile("cp.async.commit_group;");
    }

    for (int t = 0; t < ktiles; t++) {
        if (t + 1 < ktiles) asm volatile("cp.async.wait_group 1;");
        else                asm volatile("cp.async.wait_group 0;");
        __syncthreads();    // also: all warps done with tile t-1

        // issue loads for t+2 into the stage vacated by t-1, before compute
        if (t + 2 < ktiles) {
            load_tile_h(sb + (uint32_t)(((t + 2) % NSTAGE) * STAGE_BYTES),
                        A, W, m0, n0, Kd, (t + 2) * 64, tid);
            asm volatile("cp.async.commit_group;");
        }

        const uint32_t sA = sb + (uint32_t)((t % NSTAGE) * STAGE_BYTES);
        const uint32_t sB = sA + 16384u;

#pragma unroll
        for (int ks = 0; ks < 4; ks++) {
            uint32_t a[4][4], b[8][2];
#pragma unroll
            for (int mt = 0; mt < 4; mt++) {
                uint32_t off = (uint32_t)((wm + mt * 16 + (lane & 15)) * 128
                                          + ks * 32 + ((lane >> 4) << 4));
                ldsm4(a[mt][0], a[mt][1], a[mt][2], a[mt][3], sA + SWZ128(off));
            }
#pragma unroll
            for (int np = 0; np < 4; np++) {
                uint32_t off = (uint32_t)((wn + np * 16 + (lane & 7)
                                           + ((lane >> 4) & 1) * 8) * 128
                                          + ks * 32 + (((lane >> 3) & 1) << 4));
                ldsm4(b[2 * np][0], b[2 * np][1], b[2 * np + 1][0], b[2 * np + 1][1],
                      sB + SWZ128(off));
            }
#pragma unroll
            for (int mt = 0; mt < 4; mt++)
#pragma unroll
                for (int nt = 0; nt < 8; nt++)
                    mma_f16(acc[mt][nt][0], acc[mt][nt][1], acc[mt][nt][2], acc[mt][nt][3],
                            a[mt][0], a[mt][1], a[mt][2], a[mt][3],
                            b[nt][0], b[nt][1]);
        }
    }

#pragma unroll
    for (int mt = 0; mt < 4; mt++) {
#pragma unroll
        for (int nt = 0; nt < 8; nt++) {
            int row = m0 + wm + mt * 16 + gr;
            int col = n0 + wn + nt * 8 + 2 * tig;
#pragma unroll
            for (int h = 0; h < 2; h++) {
                int r = row + h * 8;
                float c0 = acc[mt][nt][h * 2 + 0];
                float c1 = acc[mt][nt][h * 2 + 1];
                if (EPI == 0) {
                    *(__half2*)((__half*)Cv + (size_t)r * N + col) =
                        __floats2half2_rn(c0, c1);
                } else if (EPI == 1) {
                    c0 = fmaxf(c0 + bias[col], 0.f);
                    c1 = fmaxf(c1 + bias[col + 1], 0.f);
                    *(__half2*)((__half*)Cv + (size_t)r * N + col) =
                        __floats2half2_rn(c0, c1);
                } else if (EPI == 2) {
                    const float2 rv = *(const float2*)(res + (size_t)r * N + col);
                    float2 o; o.x = c0 + bias[col] + rv.x; o.y = c1 + bias[col + 1] + rv.y;
                    *(float2*)((float*)Cv + (size_t)r * N + col) = o;
                } else {
                    const float2 rv = *(const float2*)(res + (size_t)r * N + col);
                    float2 o; o.x = c0 + rv.x; o.y = c1 + rv.y;
                    *(float2*)((float*)Cv + (size_t)r * N + col) = o;
                }
            }
        }
    }
}

// ---------------------------------------------------------------------------
// f32 -> fp16 converters
// ---------------------------------------------------------------------------
__global__ __launch_bounds__(256) void cvt_h(
    const float* __restrict__ in, __half* __restrict__ out)
{
    int i = blockIdx.x * blockDim.x + threadIdx.x;
    float4 v = ((const float4*)in)[i];
    ((__half2*)out)[2 * i]     = __floats2half2_rn(v.x, v.y);
    ((__half2*)out)[2 * i + 1] = __floats2half2_rn(v.z, v.w);
}

__global__ __launch_bounds__(256) void pack_qkv_h(
    const float* __restrict__ Wq, const float* __restrict__ Wk,
    const float* __restrict__ Wv, __half* __restrict__ Wp)
{
    int i = blockIdx.x * blockDim.x + threadIdx.x;
    int row = (i * 4) >> 10;
    int col = (i * 4) & 1023;
    const float* src;
    if (row < 1024)      src = Wq + (size_t)row * 1024 + col;
    else if (row < 2048) src = Wk + (size_t)(row - 1024) * 1024 + col;
    else                 src = Wv + (size_t)(row - 2048) * 1024 + col;
    float4 v = *(const float4*)src;
    ((__half2*)Wp)[2 * i]     = __floats2half2_rn(v.x, v.y);
    ((__half2*)Wp)[2 * i + 1] = __floats2half2_rn(v.z, v.w);
}

// ---------------------------------------------------------------------------
// FA2-style fp16 flash attention (unchanged from R11).
// ---------------------------------------------------------------------------
#define BQ 128
#define HSTR 72
#define Q_BYTES   (BQ * 144)
#define KV_STAGE  (2 * 64 * 144)
#define ATTN_SMEM (Q_BYTES + 2 * KV_STAGE)
#define QKV_SSTRIDE (4*3072)

__global__ __launch_bounds__(256, 2) void attn_reg(
    const __half* __restrict__ qkv, const float* __restrict__ mask,
    __half* __restrict__ u)
{
    extern __shared__ __align__(1024) char smc[];
    __half* Qh = (__half*)smc;

    const int n   = blockIdx.y;
    const int bb  = n >> 4;
    const int hh  = n & 15;
    const int s0  = blockIdx.x * BQ;
    const int tid = threadIdx.x;
    const int warp = tid >> 5;
    const int lane = tid & 31;
    const int gr   = lane >> 2;
    const int tig  = lane & 3;
    const int wq   = warp * 16;

    const uint32_t sQ  = saddr(smc);
    const uint32_t sKV = sQ + Q_BYTES;

    const __half* qb = qkv + (size_t)bb * 3072 + hh * 64;
    const __half* kb = qb + 1024;
    const __half* vb = qb + 2048;

#pragma unroll
    for (int it = 0; it < 4; it++) {
        int lin = tid + it * 256;
        int row = lin >> 3;
        int ch  = (lin & 7) * 8;
        uint4 v = *(const uint4*)(qb + (size_t)(s0 + row) * QKV_SSTRIDE + ch);
        *(uint4*)(Qh + row * HSTR + ch) = v;
    }
    __syncthreads();

    uint32_t qf[4][4];
#pragma unroll
    for (int ks = 0; ks < 4; ks++) {
        uint32_t off = (uint32_t)((wq + (lane & 15)) * 144
                                  + ks * 32 + ((lane >> 4) << 4));
        ldsm4(qf[ks][0], qf[ks][1], qf[ks][2], qf[ks][3], sQ + off);
    }
    __syncthreads();

    {
#pragma unroll
        for (int it = 0; it < 4; it++) {
            int lin = tid + it * 256;
            int row = (lin >> 3) & 63;
            int sel = lin >> 9;
            int ch  = lin & 7;
            const __half* src = (sel ? vb : kb) + (size_t)row * QKV_SSTRIDE + ch * 8;
            cp16(sKV + (uint32_t)(sel * 9216 + row * 144 + ch * 16), src);
        }
        asm volatile("cp.async.commit_group;");
    }

    float oacc[8][4];
#pragma unroll
    for (int nt = 0; nt < 8; nt++)
#pragma unroll
        for (int c = 0; c < 4; c++) oacc[nt][c] = 0.f;
    float m0r = -1e30f, m1r = -1e30f;
    float l0r = 0.f,    l1r = 0.f;

    const int NT = SEQ / 64;

    for (int t = 0; t < NT; t++) {
        asm volatile("cp.async.wait_group 0;");
        __syncthreads();

        const uint32_t sK = sKV + (uint32_t)((t & 1) * KV_STAGE);
        const uint32_t sV = sK + 9216u;

        if (t + 1 < NT) {
            const int t0n = (t + 1) * 64;
            const uint32_t dst = sKV + (uint32_t)(((t + 1) & 1) * KV_STAGE);
#pragma unroll
            for (int it = 0; it < 4; it++) {
                int lin = tid + it * 256;
                int row = (lin >> 3) & 63;
                int sel = lin >> 9;
                int ch  = lin & 7;
                const __half* src = (sel ? vb : kb)
                    + (size_t)(t0n + row) * QKV_SSTRIDE + ch * 8;
                cp16(dst + (uint32_t)(sel * 9216 + row * 144 + ch * 16), src);
            }
            asm volatile("cp.async.commit_group;");
        }

        float sacc[8][4];
#pragma unroll
        for (int nt = 0; nt < 8; nt++)
#pragma unroll
            for (int c = 0; c < 4; c++) sacc[nt][c] = 0.f;
#pragma unroll
        for (int ks = 0; ks < 4; ks++) {
#pragma unroll
            for (int np = 0; np < 4; np++) {
                uint32_t b0, b1, b2, b3;
                uint32_t off = (uint32_t)((np * 16 + (lane & 7)
                                           + ((lane >> 4) & 1) * 8) * 144
                                          + ks * 32 + (((lane >> 3) & 1) << 4));
                ldsm4(b0, b1, b2, b3, sK + off);
                mma_f16(sacc[2*np][0], sacc[2*np][1], sacc[2*np][2], sacc[2*np][3],
                        qf[ks][0], qf[ks][1], qf[ks][2], qf[ks][3], b0, b1);
                mma_f16(sacc[2*np+1][0], sacc[2*np+1][1], sacc[2*np+1][2], sacc[2*np+1][3],
                        qf[ks][0], qf[ks][1], qf[ks][2], qf[ks][3], b2, b3);
            }
        }

        const int t0 = t * 64;
        const int r0g = s0 + wq + gr;
#pragma unroll
        for (int nt = 0; nt < 8; nt++) {
            int col = t0 + nt * 8 + 2 * tig;
            const float2 mv0 = *(const float2*)(mask + (size_t)r0g * SEQ + col);
            const float2 mv1 = *(const float2*)(mask + (size_t)(r0g + 8) * SEQ + col);
            sacc[nt][0] = (sacc[nt][0] + mv0.x) * 0.125f;
            sacc[nt][1] = (sacc[nt][1] + mv0.y) * 0.125f;
            sacc[nt][2] = (sacc[nt][2] + mv1.x) * 0.125f;
            sacc[nt][3] = (sacc[nt][3] + mv1.y) * 0.125f;
        }

        float tm0 = -1e30f, tm1 = -1e30f;
#pragma unroll
        for (int nt = 0; nt < 8; nt++) {
            tm0 = fmaxf(tm0, fmaxf(sacc[nt][0], sacc[nt][1]));
            tm1 = fmaxf(tm1, fmaxf(sacc[nt][2], sacc[nt][3]));
        }
        tm0 = fmaxf(tm0, __shfl_xor_sync(0xffffffffu, tm0, 1));
        tm0 = fmaxf(tm0, __shfl_xor_sync(0xffffffffu, tm0, 2));
        tm1 = fmaxf(tm1, __shfl_xor_sync(0xffffffffu, tm1, 1));
        tm1 = fmaxf(tm1, __shfl_xor_sync(0xffffffffu, tm1, 2));

        float nm0 = fmaxf(m0r, tm0);
        float nm1 = fmaxf(m1r, tm1);
        float cr0 = __expf(m0r - nm0);
        float cr1 = __expf(m1r - nm1);
        m0r = nm0; m1r = nm1;

        uint32_t pf[4][4];
        float sum0 = 0.f, sum1 = 0.f;
#pragma unroll
        for (int j = 0; j < 4; j++) {
            float e00 = __expf(sacc[2*j][0] - nm0);
            float e01 = __expf(sacc[2*j][1] - nm0);
            float e02 = __expf(sacc[2*j][2] - nm1);
            float e03 = __expf(sacc[2*j][3] - nm1);
            float e10 = __expf(sacc[2*j+1][0] - nm0);
            float e11 = __expf(sacc[2*j+1][1] - nm0);
            float e12 = __expf(sacc[2*j+1][2] - nm1);
            float e13 = __expf(sacc[2*j+1][3] - nm1);
            sum0 += e00 + e01 + e10 + e11;
            sum1 += e02 + e03 + e12 + e13;
            pf[j][0] = h2u(__floats2half2_rn(e00, e01));
            pf[j][1] = h2u(__floats2half2_rn(e02, e03));
            pf[j][2] = h2u(__floats2half2_rn(e10, e11));
            pf[j][3] = h2u(__floats2half2_rn(e12, e13));
        }
        sum0 += __shfl_xor_sync(0xffffffffu, sum0, 1);
        sum0 += __shfl_xor_sync(0xffffffffu, sum0, 2);
        sum1 += __shfl_xor_sync(0xffffffffu, sum1, 1);
        sum1 += __shfl_xor_sync(0xffffffffu, sum1, 2);
        l0r = l0r * cr0 + sum0;
        l1r = l1r * cr1 + sum1;

#pragma unroll
        for (int nt = 0; nt < 8; nt++) {
            oacc[nt][0] *= cr0; oacc[nt][1] *= cr0;
            oacc[nt][2] *= cr1; oacc[nt][3] *= cr1;
        }
#pragma unroll
        for (int ks = 0; ks < 4; ks++) {
#pragma unroll
            for (int np = 0; np < 4; np++) {
                uint32_t b0, b1, b2, b3;
                int vrow = ks * 16 + (lane & 7) + ((lane >> 3) & 1) * 8;
                int vcol = np * 16 + ((lane >> 4) & 1) * 8;
                ldsm4_t(b0, b1, b2, b3, sV + (uint32_t)(vrow * 144 + vcol * 2));
                mma_f16(oacc[2*np][0], oacc[2*np][1], oacc[2*np][2], oacc[2*np][3],
                        pf[ks][0], pf[ks][1], pf[ks][2], pf[ks][3], b0, b1);
                mma_f16(oacc[2*np+1][0], oacc[2*np+1][1], oacc[2*np+1][2], oacc[2*np+1][3],
                        pf[ks][0], pf[ks][1], pf[ks][2], pf[ks][3], b2, b3);
            }
        }
    }

    {
        float inv0 = 1.f / l0r;
        float inv1 = 1.f / l1r;
        const int r0g = s0 + wq + gr;
#pragma unroll
        for (int nt = 0; nt < 8; nt++) {
            int col = nt * 8 + 2 * tig;
            *(__half2*)(u + (size_t)r0g * 4096 + (size_t)n * 64 + col) =
                __floats2half2_rn(oacc[nt][0] * inv0, oacc[nt][1] * inv0);
            *(__half2*)(u + (size_t)(r0g + 8) * 4096 + (size_t)n * 64 + col) =
                __floats2half2_rn(oacc[nt][2] * inv1, oacc[nt][3] * inv1);
        }
    }
}

// ---------------------------------------------------------------------------
// LayerNorm over last dim (1024); optional fp16 secondary output.
// ---------------------------------------------------------------------------
__global__ __launch_bounds__(256) void ln_kernel(
    const float* __restrict__ in, const float* __restrict__ g,
    const float* __restrict__ be, float* __restrict__ out,
    __half* __restrict__ outh)
{
    const int row = blockIdx.x;
    const int tid = threadIdx.x;
    __shared__ float red[8];
    __shared__ float s_mu, s_rstd;

    float4 v = *(const float4*)(in + (size_t)row * DMODEL + tid * 4);
    float s = v.x + v.y + v.z + v.w;
#pragma unroll
    for (int o = 16; o > 0; o >>= 1) s += __shfl_xor_sync(0xffffffffu, s, o);
    if ((tid & 31) == 0) red[tid >> 5] = s;
    __syncthreads();
    if (tid < 8) {
        float t = red[tid];
#pragma unroll
        for (int o = 4; o > 0; o >>= 1) t += __shfl_xor_sync(0xffu, t, o);
        if (tid == 0) s_mu = t * (1.f / DMODEL);
    }
    __syncthreads();
    float mu = s_mu;
    float d0 = v.x - mu, d1 = v.y - mu, d2 = v.z - mu, d3 = v.w - mu;
    float s2 = d0 * d0 + d1 * d1 + d2 * d2 + d3 * d3;
#pragma unroll
    for (int o = 16; o > 0; o >>= 1) s2 += __shfl_xor_sync(0xffffffffu, s2, o);
    if ((tid & 31) == 0) red[tid >> 5] = s2;
    __syncthreads();
    if (tid < 8) {
        float t = red[tid];
#pragma unroll
        for (int o = 4; o > 0; o >>= 1) t += __shfl_xor_sync(0xffu, t, o);
        if (tid == 0) s_rstd = rsqrtf(t * (1.f / DMODEL) + LN_EPS);
    }
    __syncthreads();
    float rstd = s_rstd;
    float4 gv = *(const float4*)(g + tid * 4);
    float4 bv = *(const float4*)(be + tid * 4);
    float4 ov;
    ov.x = d0 * rstd * gv.x + bv.x;
    ov.y = d1 * rstd * gv.y + bv.y;
    ov.z = d2 * rstd * gv.z + bv.z;
    ov.w = d3 * rstd * gv.w + bv.w;
    *(float4*)(out + (size_t)row * DMODEL + tid * 4) = ov;
    if (outh != nullptr) {
        *(__half2*)(outh + (size_t)row * DMODEL + tid * 4)     = __floats2half2_rn(ov.x, ov.y);
        *(__half2*)(outh + (size_t)row * DMODEL + tid * 4 + 2) = __floats2half2_rn(ov.z, ov.w);
    }
}

// ---------------------------------------------------------------------------
extern "C" void kernel_launch(void* const* d_in, const int* in_sizes, int n_in,
                              void* d_out, int out_size)
{
    const float* x    = (const float*)d_in[0];
    const float* mask = (const float*)d_in[1];
    const float* Wq   = (const float*)d_in[2];
    const float* Wk   = (const float*)d_in[3];
    const float* Wv   = (const float*)d_in[4];
    const float* Wc   = (const float*)d_in[5];
    const float* W1   = (const float*)d_in[6];
    const float* b1   = (const float*)d_in[7];
    const float* W2   = (const float*)d_in[8];
    const float* b2   = (const float*)d_in[9];
    const float* g1   = (const float*)d_in[10];
    const float* be1  = (const float*)d_in[11];
    const float* g2   = (const float*)d_in[12];
    const float* be2  = (const float*)d_in[13];
    float* out = (float*)d_out;

    __half *xh, *wph, *wch, *w1h, *w2h, *qkvh, *uh, *t2h, *hidh;
    float *t1, *t2, *t3;
    cudaGetSymbolAddress((void**)&xh,   g_xh);
    cudaGetSymbolAddress((void**)&wph,  g_wph);
    cudaGetSymbolAddress((void**)&wch,  g_wch);
    cudaGetSymbolAddress((void**)&w1h,  g_w1h);
    cudaGetSymbolAddress((void**)&w2h,  g_w2h);
    cudaGetSymbolAddress((void**)&qkvh, g_qkvh);
    cudaGetSymbolAddress((void**)&uh,   g_uh);
    cudaGetSymbolAddress((void**)&t2h,  g_t2h);
    cudaGetSymbolAddress((void**)&hidh, g_hidh);
    cudaGetSymbolAddress((void**)&t1,   g_t1);
    cudaGetSymbolAddress((void**)&t2,   g_t2);
    cudaGetSymbolAddress((void**)&t3,   g_t3);

    cudaFuncSetAttribute(attn_reg, cudaFuncAttributeMaxDynamicSharedMemorySize, ATTN_SMEM);
    cudaFuncSetAttribute(gemm_h, cudaFuncAttributeMaxDynamicSharedMemorySize, GEMM_SMEM_BYTES);

    dim3 blk(256);
    dim3 gblk(128);

    // fp16 conversions
    cvt_h<<<(MROWS * DMODEL / 4) / 256, blk>>>(x, xh);
    pack_qkv_h<<<(3072 * DMODEL / 4) / 256, blk>>>(Wq, Wk, Wv, wph);
    cvt_h<<<(DMODEL * DMODEL / 4) / 256, blk>>>(Wc, wch);
    cvt_h<<<(FFDIM * DMODEL / 4) / 256, blk>>>(W1, w1h);
    cvt_h<<<(DMODEL * FFDIM / 4) / 256, blk>>>(W2, w2h);

    // fused QKV projection -> qkvh fp16 [8192, 3072]
    gemm_h<<<dim3(3072 / 128, MROWS / 128), gblk, GEMM_SMEM_BYTES>>>(
        xh, wph, nullptr, nullptr, qkvh, 3072, DMODEL, 0);

    // attention -> uh fp16
    attn_reg<<<dim3(SEQ / BQ, 64), blk, ATTN_SMEM>>>(qkvh, mask, uh);

    // x + u @ Wc^T -> t1 f32;  LN1 -> t2 f32 + t2h fp16
    gemm_h<<<dim3(DMODEL / 128, MROWS / 128), gblk, GEMM_SMEM_BYTES>>>(
        uh, wch, nullptr, x, t1, DMODEL, DMODEL, 3);
    ln_kernel<<<MROWS, blk>>>(t1, g1, be1, t2, t2h);

    // FFN: relu(t2@W1^T+b1) -> hidh;  hid@W2^T+b2 + t2 -> t3;  LN2 -> out
    gemm_h<<<dim3(FFDIM / 128, MROWS / 128), gblk, GEMM_SMEM_BYTES>>>(
        t2h, w1h, b1, nullptr, hidh, FFDIM, DMODEL, 1);
    gemm_h<<<dim3(DMODEL / 128, MROWS / 128), gblk, GEMM_SMEM_BYTES>>>(
        hidh, w2h, b2, t2, t3, DMODEL, FFDIM, 2);
    ln_kernel<<<MROWS, blk>>>(t3, g2, be2, out, nullptr);
}

// round 15
// speedup vs baseline: 1.0423x; 1.0423x over previous
#include <cuda_runtime.h>
#include <cuda_fp16.h>
#include <math.h>
#include <stdint.h>

// ---------------------------------------------------------------------------
// PTransformerBlock: S=2048 B=4 D=1024 H=16 K=64 FF=4096.
// Round 15: fp16 mask (halves attention's 1GB mask L2 traffic),
//           GEMM back to R13 best config, FA2 attention.
// ---------------------------------------------------------------------------

#define SEQ   2048
#define BATCH 4
#define DMODEL 1024
#define FFDIM 4096
#define MROWS (SEQ*BATCH)   // 8192
#define LN_EPS 1e-5f

// scratch (allocation-free: device globals)
__device__ __half g_xh   [MROWS * DMODEL];
__device__ __half g_wph  [3072 * DMODEL];
__device__ __half g_wch  [DMODEL * DMODEL];
__device__ __half g_w1h  [FFDIM * DMODEL];
__device__ __half g_w2h  [DMODEL * FFDIM];
__device__ __half g_maskh[SEQ * SEQ];
__device__ __half g_qkvh [MROWS * 3072];
__device__ __half g_uh   [MROWS * DMODEL];
__device__ __half g_t2h  [MROWS * DMODEL];
__device__ __half g_hidh [MROWS * FFDIM];
__device__ float  g_t1   [MROWS * DMODEL];
__device__ float  g_t2   [MROWS * DMODEL];
__device__ float  g_t3   [MROWS * DMODEL];

__device__ __forceinline__ uint32_t h2u(__half2 h) {
    union { __half2 h; uint32_t u; } c;
    c.h = h;
    return c.u;
}

__device__ __forceinline__ void mma_f16(
    float& d0, float& d1, float& d2, float& d3,
    uint32_t a0, uint32_t a1, uint32_t a2, uint32_t a3,
    uint32_t b0, uint32_t b1)
{
    asm volatile(
        "mma.sync.aligned.m16n8k16.row.col.f32.f16.f16.f32 "
        "{%0,%1,%2,%3}, {%4,%5,%6,%7}, {%8,%9}, {%0,%1,%2,%3};"
        : "+f"(d0), "+f"(d1), "+f"(d2), "+f"(d3)
        : "r"(a0), "r"(a1), "r"(a2), "r"(a3), "r"(b0), "r"(b1));
}

__device__ __forceinline__ void ldsm4(
    uint32_t& r0, uint32_t& r1, uint32_t& r2, uint32_t& r3, uint32_t addr)
{
    asm volatile("ldmatrix.sync.aligned.m8n8.x4.shared.b16 {%0,%1,%2,%3}, [%4];"
                 : "=r"(r0), "=r"(r1), "=r"(r2), "=r"(r3) : "r"(addr));
}
__device__ __forceinline__ void ldsm4_t(
    uint32_t& r0, uint32_t& r1, uint32_t& r2, uint32_t& r3, uint32_t addr)
{
    asm volatile("ldmatrix.sync.aligned.m8n8.x4.trans.shared.b16 {%0,%1,%2,%3}, [%4];"
                 : "=r"(r0), "=r"(r1), "=r"(r2), "=r"(r3) : "r"(addr));
}

__device__ __forceinline__ void cp16(uint32_t s, const void* g) {
    asm volatile("cp.async.cg.shared.global [%0], [%1], 16;" :: "r"(s), "l"(g));
}
__device__ __forceinline__ uint32_t saddr(const void* p) {
    return (uint32_t)__cvta_generic_to_shared(p);
}
#define SWZ128(o) ((o) ^ (((o) >> 3) & 0x70))

// ---------------------------------------------------------------------------
// fp16 tensor-core GEMM (R13 best config: 128x128 CTA, 64x32 warp tiles,
// 2 CTAs/SM, 3-stage cp.async, one __syncthreads per k-tile).
// EPI: 0=none,fp16  1=+bias,relu,fp16  2=+bias,+res,f32  3=+res,f32
// ---------------------------------------------------------------------------
#define STAGE_BYTES 32768
#define NSTAGE 3
#define GEMM_SMEM_BYTES (NSTAGE * STAGE_BYTES)

__device__ __forceinline__ void load_tile_h(
    uint32_t base, const __half* __restrict__ A, const __half* __restrict__ W,
    int m0, int n0, int Kd, int k0, int tid)
{
#pragma unroll
    for (int it = 0; it < 4; it++) {
        int lin = tid + it * 256;
        int row = lin >> 3;
        int ch  = lin & 7;
        uint32_t off = (uint32_t)(row * 128 + ch * 16);
        uint32_t sw  = SWZ128(off);
        cp16(base + sw,         A + (size_t)(m0 + row) * Kd + k0 + ch * 8);
        cp16(base + 16384 + sw, W + (size_t)(n0 + row) * Kd + k0 + ch * 8);
    }
}

__global__ __launch_bounds__(256, 2) void gemm_h(
    const __half* __restrict__ A, const __half* __restrict__ W,
    const float* __restrict__ bias, const float* __restrict__ res,
    void* __restrict__ Cv, int N, int Kd, int EPI)
{
    extern __shared__ __align__(1024) char smem[];

    const int tid  = threadIdx.x;
    const int warp = tid >> 5;
    const int lane = tid & 31;
    const int gr   = lane >> 2;
    const int tig  = lane & 3;
    const int wm   = (warp & 1) * 64;
    const int wn   = (warp >> 1) * 32;
    const int m0   = blockIdx.y * 128;
    const int n0   = blockIdx.x * 128;

    const uint32_t sb = saddr(smem);

    float acc[4][4][4];
#pragma unroll
    for (int mt = 0; mt < 4; mt++)
#pragma unroll
        for (int nt = 0; nt < 4; nt++)
#pragma unroll
            for (int c = 0; c < 4; c++) acc[mt][nt][c] = 0.f;

    const int ktiles = Kd >> 6;

#pragma unroll
    for (int pf = 0; pf < 2; pf++) {
        load_tile_h(sb + pf * STAGE_BYTES, A, W, m0, n0, Kd, pf * 64, tid);
        asm volatile("cp.async.commit_group;");
    }

    for (int t = 0; t < ktiles; t++) {
        if (t + 1 < ktiles) asm volatile("cp.async.wait_group 1;");
        else                asm volatile("cp.async.wait_group 0;");
        __syncthreads();

        if (t + 2 < ktiles) {
            load_tile_h(sb + (uint32_t)(((t + 2) % NSTAGE) * STAGE_BYTES),
                        A, W, m0, n0, Kd, (t + 2) * 64, tid);
            asm volatile("cp.async.commit_group;");
        }

        const uint32_t sA = sb + (uint32_t)((t % NSTAGE) * STAGE_BYTES);
        const uint32_t sB = sA + 16384u;

#pragma unroll
        for (int ks = 0; ks < 4; ks++) {
            uint32_t a[4][4], b[4][2];
#pragma unroll
            for (int mt = 0; mt < 4; mt++) {
                uint32_t off = (uint32_t)((wm + mt * 16 + (lane & 15)) * 128
                                          + ks * 32 + ((lane >> 4) << 4));
                ldsm4(a[mt][0], a[mt][1], a[mt][2], a[mt][3], sA + SWZ128(off));
            }
#pragma unroll
            for (int np = 0; np < 2; np++) {
                uint32_t off = (uint32_t)((wn + np * 16 + (lane & 7)
                                           + ((lane >> 4) & 1) * 8) * 128
                                          + ks * 32 + (((lane >> 3) & 1) << 4));
                ldsm4(b[2 * np][0], b[2 * np][1], b[2 * np + 1][0], b[2 * np + 1][1],
                      sB + SWZ128(off));
            }
#pragma unroll
            for (int mt = 0; mt < 4; mt++)
#pragma unroll
                for (int nt = 0; nt < 4; nt++)
                    mma_f16(acc[mt][nt][0], acc[mt][nt][1], acc[mt][nt][2], acc[mt][nt][3],
                            a[mt][0], a[mt][1], a[mt][2], a[mt][3],
                            b[nt][0], b[nt][1]);
        }
    }

#pragma unroll
    for (int mt = 0; mt < 4; mt++) {
#pragma unroll
        for (int nt = 0; nt < 4; nt++) {
            int row = m0 + wm + mt * 16 + gr;
            int col = n0 + wn + nt * 8 + 2 * tig;
#pragma unroll
            for (int h = 0; h < 2; h++) {
                int r = row + h * 8;
                float c0 = acc[mt][nt][h * 2 + 0];
                float c1 = acc[mt][nt][h * 2 + 1];
                if (EPI == 0) {
                    *(__half2*)((__half*)Cv + (size_t)r * N + col) =
                        __floats2half2_rn(c0, c1);
                } else if (EPI == 1) {
                    c0 = fmaxf(c0 + bias[col], 0.f);
                    c1 = fmaxf(c1 + bias[col + 1], 0.f);
                    *(__half2*)((__half*)Cv + (size_t)r * N + col) =
                        __floats2half2_rn(c0, c1);
                } else if (EPI == 2) {
                    const float2 rv = *(const float2*)(res + (size_t)r * N + col);
                    float2 o; o.x = c0 + bias[col] + rv.x; o.y = c1 + bias[col + 1] + rv.y;
                    *(float2*)((float*)Cv + (size_t)r * N + col) = o;
                } else {
                    const float2 rv = *(const float2*)(res + (size_t)r * N + col);
                    float2 o; o.x = c0 + rv.x; o.y = c1 + rv.y;
                    *(float2*)((float*)Cv + (size_t)r * N + col) = o;
                }
            }
        }
    }
}

// ---------------------------------------------------------------------------
// f32 -> fp16 converters
// ---------------------------------------------------------------------------
__global__ __launch_bounds__(256) void cvt_h(
    const float* __restrict__ in, __half* __restrict__ out)
{
    int i = blockIdx.x * blockDim.x + threadIdx.x;
    float4 v = ((const float4*)in)[i];
    ((__half2*)out)[2 * i]     = __floats2half2_rn(v.x, v.y);
    ((__half2*)out)[2 * i + 1] = __floats2half2_rn(v.z, v.w);
}

__global__ __launch_bounds__(256) void pack_qkv_h(
    const float* __restrict__ Wq, const float* __restrict__ Wk,
    const float* __restrict__ Wv, __half* __restrict__ Wp)
{
    int i = blockIdx.x * blockDim.x + threadIdx.x;
    int row = (i * 4) >> 10;
    int col = (i * 4) & 1023;
    const float* src;
    if (row < 1024)      src = Wq + (size_t)row * 1024 + col;
    else if (row < 2048) src = Wk + (size_t)(row - 1024) * 1024 + col;
    else                 src = Wv + (size_t)(row - 2048) * 1024 + col;
    float4 v = *(const float4*)src;
    ((__half2*)Wp)[2 * i]     = __floats2half2_rn(v.x, v.y);
    ((__half2*)Wp)[2 * i + 1] = __floats2half2_rn(v.z, v.w);
}

// ---------------------------------------------------------------------------
// FA2-style fp16 flash attention (R11) with fp16 mask.
// ---------------------------------------------------------------------------
#define BQ 128
#define HSTR 72
#define Q_BYTES   (BQ * 144)
#define KV_STAGE  (2 * 64 * 144)
#define ATTN_SMEM (Q_BYTES + 2 * KV_STAGE)
#define QKV_SSTRIDE (4*3072)

__global__ __launch_bounds__(256, 2) void attn_reg(
    const __half* __restrict__ qkv, const __half* __restrict__ maskh,
    __half* __restrict__ u)
{
    extern __shared__ __align__(1024) char smc[];
    __half* Qh = (__half*)smc;

    const int n   = blockIdx.y;
    const int bb  = n >> 4;
    const int hh  = n & 15;
    const int s0  = blockIdx.x * BQ;
    const int tid = threadIdx.x;
    const int warp = tid >> 5;
    const int lane = tid & 31;
    const int gr   = lane >> 2;
    const int tig  = lane & 3;
    const int wq   = warp * 16;

    const uint32_t sQ  = saddr(smc);
    const uint32_t sKV = sQ + Q_BYTES;

    const __half* qb = qkv + (size_t)bb * 3072 + hh * 64;
    const __half* kb = qb + 1024;
    const __half* vb = qb + 2048;

#pragma unroll
    for (int it = 0; it < 4; it++) {
        int lin = tid + it * 256;
        int row = lin >> 3;
        int ch  = (lin & 7) * 8;
        uint4 v = *(const uint4*)(qb + (size_t)(s0 + row) * QKV_SSTRIDE + ch);
        *(uint4*)(Qh + row * HSTR + ch) = v;
    }
    __syncthreads();

    uint32_t qf[4][4];
#pragma unroll
    for (int ks = 0; ks < 4; ks++) {
        uint32_t off = (uint32_t)((wq + (lane & 15)) * 144
                                  + ks * 32 + ((lane >> 4) << 4));
        ldsm4(qf[ks][0], qf[ks][1], qf[ks][2], qf[ks][3], sQ + off);
    }
    __syncthreads();

    {
#pragma unroll
        for (int it = 0; it < 4; it++) {
            int lin = tid + it * 256;
            int row = (lin >> 3) & 63;
            int sel = lin >> 9;
            int ch  = lin & 7;
            const __half* src = (sel ? vb : kb) + (size_t)row * QKV_SSTRIDE + ch * 8;
            cp16(sKV + (uint32_t)(sel * 9216 + row * 144 + ch * 16), src);
        }
        asm volatile("cp.async.commit_group;");
    }

    float oacc[8][4];
#pragma unroll
    for (int nt = 0; nt < 8; nt++)
#pragma unroll
        for (int c = 0; c < 4; c++) oacc[nt][c] = 0.f;
    float m0r = -1e30f, m1r = -1e30f;
    float l0r = 0.f,    l1r = 0.f;

    const int NT = SEQ / 64;

    for (int t = 0; t < NT; t++) {
        asm volatile("cp.async.wait_group 0;");
        __syncthreads();

        const uint32_t sK = sKV + (uint32_t)((t & 1) * KV_STAGE);
        const uint32_t sV = sK + 9216u;

        if (t + 1 < NT) {
            const int t0n = (t + 1) * 64;
            const uint32_t dst = sKV + (uint32_t)(((t + 1) & 1) * KV_STAGE);
#pragma unroll
            for (int it = 0; it < 4; it++) {
                int lin = tid + it * 256;
                int row = (lin >> 3) & 63;
                int sel = lin >> 9;
                int ch  = lin & 7;
                const __half* src = (sel ? vb : kb)
                    + (size_t)(t0n + row) * QKV_SSTRIDE + ch * 8;
                cp16(dst + (uint32_t)(sel * 9216 + row * 144 + ch * 16), src);
            }
            asm volatile("cp.async.commit_group;");
        }

        float sacc[8][4];
#pragma unroll
        for (int nt = 0; nt < 8; nt++)
#pragma unroll
            for (int c = 0; c < 4; c++) sacc[nt][c] = 0.f;
#pragma unroll
        for (int ks = 0; ks < 4; ks++) {
#pragma unroll
            for (int np = 0; np < 4; np++) {
                uint32_t b0, b1, b2, b3;
                uint32_t off = (uint32_t)((np * 16 + (lane & 7)
                                           + ((lane >> 4) & 1) * 8) * 144
                                          + ks * 32 + (((lane >> 3) & 1) << 4));
                ldsm4(b0, b1, b2, b3, sK + off);
                mma_f16(sacc[2*np][0], sacc[2*np][1], sacc[2*np][2], sacc[2*np][3],
                        qf[ks][0], qf[ks][1], qf[ks][2], qf[ks][3], b0, b1);
                mma_f16(sacc[2*np+1][0], sacc[2*np+1][1], sacc[2*np+1][2], sacc[2*np+1][3],
                        qf[ks][0], qf[ks][1], qf[ks][2], qf[ks][3], b2, b3);
            }
        }

        // mask (fp16, BEFORE scale) + scale, in registers
        const int t0 = t * 64;
        const int r0g = s0 + wq + gr;
#pragma unroll
        for (int nt = 0; nt < 8; nt++) {
            int col = t0 + nt * 8 + 2 * tig;
            const float2 mv0 = __half22float2(
                *(const __half2*)(maskh + (size_t)r0g * SEQ + col));
            const float2 mv1 = __half22float2(
                *(const __half2*)(maskh + (size_t)(r0g + 8) * SEQ + col));
            sacc[nt][0] = (sacc[nt][0] + mv0.x) * 0.125f;
            sacc[nt][1] = (sacc[nt][1] + mv0.y) * 0.125f;
            sacc[nt][2] = (sacc[nt][2] + mv1.x) * 0.125f;
            sacc[nt][3] = (sacc[nt][3] + mv1.y) * 0.125f;
        }

        float tm0 = -1e30f, tm1 = -1e30f;
#pragma unroll
        for (int nt = 0; nt < 8; nt++) {
            tm0 = fmaxf(tm0, fmaxf(sacc[nt][0], sacc[nt][1]));
            tm1 = fmaxf(tm1, fmaxf(sacc[nt][2], sacc[nt][3]));
        }
        tm0 = fmaxf(tm0, __shfl_xor_sync(0xffffffffu, tm0, 1));
        tm0 = fmaxf(tm0, __shfl_xor_sync(0xffffffffu, tm0, 2));
        tm1 = fmaxf(tm1, __shfl_xor_sync(0xffffffffu, tm1, 1));
        tm1 = fmaxf(tm1, __shfl_xor_sync(0xffffffffu, tm1, 2));

        float nm0 = fmaxf(m0r, tm0);
        float nm1 = fmaxf(m1r, tm1);
        float cr0 = __expf(m0r - nm0);
        float cr1 = __expf(m1r - nm1);
        m0r = nm0; m1r = nm1;

        uint32_t pf[4][4];
        float sum0 = 0.f, sum1 = 0.f;
#pragma unroll
        for (int j = 0; j < 4; j++) {
            float e00 = __expf(sacc[2*j][0] - nm0);
            float e01 = __expf(sacc[2*j][1] - nm0);
            float e02 = __expf(sacc[2*j][2] - nm1);
            float e03 = __expf(sacc[2*j][3] - nm1);
            float e10 = __expf(sacc[2*j+1][0] - nm0);
            float e11 = __expf(sacc[2*j+1][1] - nm0);
            float e12 = __expf(sacc[2*j+1][2] - nm1);
            float e13 = __expf(sacc[2*j+1][3] - nm1);
            sum0 += e00 + e01 + e10 + e11;
            sum1 += e02 + e03 + e12 + e13;
            pf[j][0] = h2u(__floats2half2_rn(e00, e01));
            pf[j][1] = h2u(__floats2half2_rn(e02, e03));
            pf[j][2] = h2u(__floats2half2_rn(e10, e11));
            pf[j][3] = h2u(__floats2half2_rn(e12, e13));
        }
        sum0 += __shfl_xor_sync(0xffffffffu, sum0, 1);
        sum0 += __shfl_xor_sync(0xffffffffu, sum0, 2);
        sum1 += __shfl_xor_sync(0xffffffffu, sum1, 1);
        sum1 += __shfl_xor_sync(0xffffffffu, sum1, 2);
        l0r = l0r * cr0 + sum0;
        l1r = l1r * cr1 + sum1;

#pragma unroll
        for (int nt = 0; nt < 8; nt++) {
            oacc[nt][0] *= cr0; oacc[nt][1] *= cr0;
            oacc[nt][2] *= cr1; oacc[nt][3] *= cr1;
        }
#pragma unroll
        for (int ks = 0; ks < 4; ks++) {
#pragma unroll
            for (int np = 0; np < 4; np++) {
                uint32_t b0, b1, b2, b3;
                int vrow = ks * 16 + (lane & 7) + ((lane >> 3) & 1) * 8;
                int vcol = np * 16 + ((lane >> 4) & 1) * 8;
                ldsm4_t(b0, b1, b2, b3, sV + (uint32_t)(vrow * 144 + vcol * 2));
                mma_f16(oacc[2*np][0], oacc[2*np][1], oacc[2*np][2], oacc[2*np][3],
                        pf[ks][0], pf[ks][1], pf[ks][2], pf[ks][3], b0, b1);
                mma_f16(oacc[2*np+1][0], oacc[2*np+1][1], oacc[2*np+1][2], oacc[2*np+1][3],
                        pf[ks][0], pf[ks][1], pf[ks][2], pf[ks][3], b2, b3);
            }
        }
    }

    {
        float inv0 = 1.f / l0r;
        float inv1 = 1.f / l1r;
        const int r0g = s0 + wq + gr;
#pragma unroll
        for (int nt = 0; nt < 8; nt++) {
            int col = nt * 8 + 2 * tig;
            *(__half2*)(u + (size_t)r0g * 4096 + (size_t)n * 64 + col) =
                __floats2half2_rn(oacc[nt][0] * inv0, oacc[nt][1] * inv0);
            *(__half2*)(u + (size_t)(r0g + 8) * 4096 + (size_t)n * 64 + col) =
                __floats2half2_rn(oacc[nt][2] * inv1, oacc[nt][3] * inv1);
        }
    }
}

// ---------------------------------------------------------------------------
// LayerNorm over last dim (1024); optional fp16 secondary output.
// ---------------------------------------------------------------------------
__global__ __launch_bounds__(256) void ln_kernel(
    const float* __restrict__ in, const float* __restrict__ g,
    const float* __restrict__ be, float* __restrict__ out,
    __half* __restrict__ outh)
{
    const int row = blockIdx.x;
    const int tid = threadIdx.x;
    __shared__ float red[8];
    __shared__ float s_mu, s_rstd;

    float4 v = *(const float4*)(in + (size_t)row * DMODEL + tid * 4);
    float s = v.x + v.y + v.z + v.w;
#pragma unroll
    for (int o = 16; o > 0; o >>= 1) s += __shfl_xor_sync(0xffffffffu, s, o);
    if ((tid & 31) == 0) red[tid >> 5] = s;
    __syncthreads();
    if (tid < 8) {
        float t = red[tid];
#pragma unroll
        for (int o = 4; o > 0; o >>= 1) t += __shfl_xor_sync(0xffu, t, o);
        if (tid == 0) s_mu = t * (1.f / DMODEL);
    }
    __syncthreads();
    float mu = s_mu;
    float d0 = v.x - mu, d1 = v.y - mu, d2 = v.z - mu, d3 = v.w - mu;
    float s2 = d0 * d0 + d1 * d1 + d2 * d2 + d3 * d3;
#pragma unroll
    for (int o = 16; o > 0; o >>= 1) s2 += __shfl_xor_sync(0xffffffffu, s2, o);
    if ((tid & 31) == 0) red[tid >> 5] = s2;
    __syncthreads();
    if (tid < 8) {
        float t = red[tid];
#pragma unroll
        for (int o = 4; o > 0; o >>= 1) t += __shfl_xor_sync(0xffu, t, o);
        if (tid == 0) s_rstd = rsqrtf(t * (1.f / DMODEL) + LN_EPS);
    }
    __syncthreads();
    float rstd = s_rstd;
    float4 gv = *(const float4*)(g + tid * 4);
    float4 bv = *(const float4*)(be + tid * 4);
    float4 ov;
    ov.x = d0 * rstd * gv.x + bv.x;
    ov.y = d1 * rstd * gv.y + bv.y;
    ov.z = d2 * rstd * gv.z + bv.z;
    ov.w = d3 * rstd * gv.w + bv.w;
    *(float4*)(out + (size_t)row * DMODEL + tid * 4) = ov;
    if (outh != nullptr) {
        *(__half2*)(outh + (size_t)row * DMODEL + tid * 4)     = __floats2half2_rn(ov.x, ov.y);
        *(__half2*)(outh + (size_t)row * DMODEL + tid * 4 + 2) = __floats2half2_rn(ov.z, ov.w);
    }
}

// ---------------------------------------------------------------------------
extern "C" void kernel_launch(void* const* d_in, const int* in_sizes, int n_in,
                              void* d_out, int out_size)
{
    const float* x    = (const float*)d_in[0];
    const float* mask = (const float*)d_in[1];
    const float* Wq   = (const float*)d_in[2];
    const float* Wk   = (const float*)d_in[3];
    const float* Wv   = (const float*)d_in[4];
    const float* Wc   = (const float*)d_in[5];
    const float* W1   = (const float*)d_in[6];
    const float* b1   = (const float*)d_in[7];
    const float* W2   = (const float*)d_in[8];
    const float* b2   = (const float*)d_in[9];
    const float* g1   = (const float*)d_in[10];
    const float* be1  = (const float*)d_in[11];
    const float* g2   = (const float*)d_in[12];
    const float* be2  = (const float*)d_in[13];
    float* out = (float*)d_out;

    __half *xh, *wph, *wch, *w1h, *w2h, *maskh, *qkvh, *uh, *t2h, *hidh;
    float *t1, *t2, *t3;
    cudaGetSymbolAddress((void**)&xh,    g_xh);
    cudaGetSymbolAddress((void**)&wph,   g_wph);
    cudaGetSymbolAddress((void**)&wch,   g_wch);
    cudaGetSymbolAddress((void**)&w1h,   g_w1h);
    cudaGetSymbolAddress((void**)&w2h,   g_w2h);
    cudaGetSymbolAddress((void**)&maskh, g_maskh);
    cudaGetSymbolAddress((void**)&qkvh,  g_qkvh);
    cudaGetSymbolAddress((void**)&uh,    g_uh);
    cudaGetSymbolAddress((void**)&t2h,   g_t2h);
    cudaGetSymbolAddress((void**)&hidh,  g_hidh);
    cudaGetSymbolAddress((void**)&t1,    g_t1);
    cudaGetSymbolAddress((void**)&t2,    g_t2);
    cudaGetSymbolAddress((void**)&t3,    g_t3);

    cudaFuncSetAttribute(attn_reg, cudaFuncAttributeMaxDynamicSharedMemorySize, ATTN_SMEM);
    cudaFuncSetAttribute(gemm_h, cudaFuncAttributeMaxDynamicSharedMemorySize, GEMM_SMEM_BYTES);

    dim3 blk(256);

    // fp16 conversions (x, weights, mask)
    cvt_h<<<(MROWS * DMODEL / 4) / 256, blk>>>(x, xh);
    pack_qkv_h<<<(3072 * DMODEL / 4) / 256, blk>>>(Wq, Wk, Wv, wph);
    cvt_h<<<(DMODEL * DMODEL / 4) / 256, blk>>>(Wc, wch);
    cvt_h<<<(FFDIM * DMODEL / 4) / 256, blk>>>(W1, w1h);
    cvt_h<<<(DMODEL * FFDIM / 4) / 256, blk>>>(W2, w2h);
    cvt_h<<<(SEQ * SEQ / 4) / 256, blk>>>(mask, maskh);

    // fused QKV projection -> qkvh fp16 [8192, 3072]
    gemm_h<<<dim3(3072 / 128, MROWS / 128), blk, GEMM_SMEM_BYTES>>>(
        xh, wph, nullptr, nullptr, qkvh, 3072, DMODEL, 0);

    // attention -> uh fp16
    attn_reg<<<dim3(SEQ / BQ, 64), blk, ATTN_SMEM>>>(qkvh, maskh, uh);

    // x + u @ Wc^T -> t1 f32;  LN1 -> t2 f32 + t2h fp16
    gemm_h<<<dim3(DMODEL / 128, MROWS / 128), blk, GEMM_SMEM_BYTES>>>(
        uh, wch, nullptr, x, t1, DMODEL, DMODEL, 3);
    ln_kernel<<<MROWS, blk>>>(t1, g1, be1, t2, t2h);

    // FFN: relu(t2@W1^T+b1) -> hidh;  hid@W2^T+b2 + t2 -> t3;  LN2 -> out
    gemm_h<<<dim3(FFDIM / 128, MROWS / 128), blk, GEMM_SMEM_BYTES>>>(
        t2h, w1h, b1, nullptr, hidh, FFDIM, DMODEL, 1);
    gemm_h<<<dim3(DMODEL / 128, MROWS / 128), blk, GEMM_SMEM_BYTES>>>(
        hidh, w2h, b2, t2, t3, DMODEL, FFDIM, 2);
    ln_kernel<<<MROWS, blk>>>(t3, g2, be2, out, nullptr);
}

// round 16
// speedup vs baseline: 1.0565x; 1.0136x over previous
#include <cuda_runtime.h>
#include <cuda_fp16.h>
#include <math.h>
#include <stdint.h>

// ---------------------------------------------------------------------------
// PTransformerBlock: S=2048 B=4 D=1024 H=16 K=64 FF=4096.
// Round 16: wider f32->fp16 converters (8 floats/thread), fp16 residual
//           stream t1/t3 (LN reads fp16). GEMM/attention at R15 best.
// ---------------------------------------------------------------------------

#define SEQ   2048
#define BATCH 4
#define DMODEL 1024
#define FFDIM 4096
#define MROWS (SEQ*BATCH)   // 8192
#define LN_EPS 1e-5f

// scratch (allocation-free: device globals)
__device__ __half g_xh   [MROWS * DMODEL];
__device__ __half g_wph  [3072 * DMODEL];
__device__ __half g_wch  [DMODEL * DMODEL];
__device__ __half g_w1h  [FFDIM * DMODEL];
__device__ __half g_w2h  [DMODEL * FFDIM];
__device__ __half g_maskh[SEQ * SEQ];
__device__ __half g_qkvh [MROWS * 3072];
__device__ __half g_uh   [MROWS * DMODEL];
__device__ __half g_t1h  [MROWS * DMODEL];
__device__ __half g_t2h  [MROWS * DMODEL];
__device__ __half g_t3h  [MROWS * DMODEL];
__device__ __half g_hidh [MROWS * FFDIM];
__device__ float  g_t2   [MROWS * DMODEL];

__device__ __forceinline__ uint32_t h2u(__half2 h) {
    union { __half2 h; uint32_t u; } c;
    c.h = h;
    return c.u;
}

__device__ __forceinline__ void mma_f16(
    float& d0, float& d1, float& d2, float& d3,
    uint32_t a0, uint32_t a1, uint32_t a2, uint32_t a3,
    uint32_t b0, uint32_t b1)
{
    asm volatile(
        "mma.sync.aligned.m16n8k16.row.col.f32.f16.f16.f32 "
        "{%0,%1,%2,%3}, {%4,%5,%6,%7}, {%8,%9}, {%0,%1,%2,%3};"
        : "+f"(d0), "+f"(d1), "+f"(d2), "+f"(d3)
        : "r"(a0), "r"(a1), "r"(a2), "r"(a3), "r"(b0), "r"(b1));
}

__device__ __forceinline__ void ldsm4(
    uint32_t& r0, uint32_t& r1, uint32_t& r2, uint32_t& r3, uint32_t addr)
{
    asm volatile("ldmatrix.sync.aligned.m8n8.x4.shared.b16 {%0,%1,%2,%3}, [%4];"
                 : "=r"(r0), "=r"(r1), "=r"(r2), "=r"(r3) : "r"(addr));
}
__device__ __forceinline__ void ldsm4_t(
    uint32_t& r0, uint32_t& r1, uint32_t& r2, uint32_t& r3, uint32_t addr)
{
    asm volatile("ldmatrix.sync.aligned.m8n8.x4.trans.shared.b16 {%0,%1,%2,%3}, [%4];"
                 : "=r"(r0), "=r"(r1), "=r"(r2), "=r"(r3) : "r"(addr));
}

__device__ __forceinline__ void cp16(uint32_t s, const void* g) {
    asm volatile("cp.async.cg.shared.global [%0], [%1], 16;" :: "r"(s), "l"(g));
}
__device__ __forceinline__ uint32_t saddr(const void* p) {
    return (uint32_t)__cvta_generic_to_shared(p);
}
#define SWZ128(o) ((o) ^ (((o) >> 3) & 0x70))

// ---------------------------------------------------------------------------
// fp16 tensor-core GEMM (R13/R15 config).
// EPI: 0=none,fp16  1=+bias,relu,fp16
//      2=+bias,+res(f32),out fp16   3=+res(f32),out fp16
// ---------------------------------------------------------------------------
#define STAGE_BYTES 32768
#define NSTAGE 3
#define GEMM_SMEM_BYTES (NSTAGE * STAGE_BYTES)

__device__ __forceinline__ void load_tile_h(
    uint32_t base, const __half* __restrict__ A, const __half* __restrict__ W,
    int m0, int n0, int Kd, int k0, int tid)
{
#pragma unroll
    for (int it = 0; it < 4; it++) {
        int lin = tid + it * 256;
        int row = lin >> 3;
        int ch  = lin & 7;
        uint32_t off = (uint32_t)(row * 128 + ch * 16);
        uint32_t sw  = SWZ128(off);
        cp16(base + sw,         A + (size_t)(m0 + row) * Kd + k0 + ch * 8);
        cp16(base + 16384 + sw, W + (size_t)(n0 + row) * Kd + k0 + ch * 8);
    }
}

__global__ __launch_bounds__(256, 2) void gemm_h(
    const __half* __restrict__ A, const __half* __restrict__ W,
    const float* __restrict__ bias, const float* __restrict__ res,
    __half* __restrict__ C, int N, int Kd, int EPI)
{
    extern __shared__ __align__(1024) char smem[];

    const int tid  = threadIdx.x;
    const int warp = tid >> 5;
    const int lane = tid & 31;
    const int gr   = lane >> 2;
    const int tig  = lane & 3;
    const int wm   = (warp & 1) * 64;
    const int wn   = (warp >> 1) * 32;
    const int m0   = blockIdx.y * 128;
    const int n0   = blockIdx.x * 128;

    const uint32_t sb = saddr(smem);

    float acc[4][4][4];
#pragma unroll
    for (int mt = 0; mt < 4; mt++)
#pragma unroll
        for (int nt = 0; nt < 4; nt++)
#pragma unroll
            for (int c = 0; c < 4; c++) acc[mt][nt][c] = 0.f;

    const int ktiles = Kd >> 6;

#pragma unroll
    for (int pf = 0; pf < 2; pf++) {
        load_tile_h(sb + pf * STAGE_BYTES, A, W, m0, n0, Kd, pf * 64, tid);
        asm volatile("cp.async.commit_group;");
    }

    for (int t = 0; t < ktiles; t++) {
        if (t + 1 < ktiles) asm volatile("cp.async.wait_group 1;");
        else                asm volatile("cp.async.wait_group 0;");
        __syncthreads();

        if (t + 2 < ktiles) {
            load_tile_h(sb + (uint32_t)(((t + 2) % NSTAGE) * STAGE_BYTES),
                        A, W, m0, n0, Kd, (t + 2) * 64, tid);
            asm volatile("cp.async.commit_group;");
        }

        const uint32_t sA = sb + (uint32_t)((t % NSTAGE) * STAGE_BYTES);
        const uint32_t sB = sA + 16384u;

#pragma unroll
        for (int ks = 0; ks < 4; ks++) {
            uint32_t a[4][4], b[4][2];
#pragma unroll
            for (int mt = 0; mt < 4; mt++) {
                uint32_t off = (uint32_t)((wm + mt * 16 + (lane & 15)) * 128
                                          + ks * 32 + ((lane >> 4) << 4));
                ldsm4(a[mt][0], a[mt][1], a[mt][2], a[mt][3], sA + SWZ128(off));
            }
#pragma unroll
            for (int np = 0; np < 2; np++) {
                uint32_t off = (uint32_t)((wn + np * 16 + (lane & 7)
                                           + ((lane >> 4) & 1) * 8) * 128
                                          + ks * 32 + (((lane >> 3) & 1) << 4));
                ldsm4(b[2 * np][0], b[2 * np][1], b[2 * np + 1][0], b[2 * np + 1][1],
                      sB + SWZ128(off));
            }
#pragma unroll
            for (int mt = 0; mt < 4; mt++)
#pragma unroll
                for (int nt = 0; nt < 4; nt++)
                    mma_f16(acc[mt][nt][0], acc[mt][nt][1], acc[mt][nt][2], acc[mt][nt][3],
                            a[mt][0], a[mt][1], a[mt][2], a[mt][3],
                            b[nt][0], b[nt][1]);
        }
    }

#pragma unroll
    for (int mt = 0; mt < 4; mt++) {
#pragma unroll
        for (int nt = 0; nt < 4; nt++) {
            int row = m0 + wm + mt * 16 + gr;
            int col = n0 + wn + nt * 8 + 2 * tig;
#pragma unroll
            for (int h = 0; h < 2; h++) {
                int r = row + h * 8;
                float c0 = acc[mt][nt][h * 2 + 0];
                float c1 = acc[mt][nt][h * 2 + 1];
                if (EPI == 1) {
                    c0 = fmaxf(c0 + bias[col], 0.f);
                    c1 = fmaxf(c1 + bias[col + 1], 0.f);
                } else if (EPI == 2) {
                    const float2 rv = *(const float2*)(res + (size_t)r * N + col);
                    c0 += bias[col] + rv.x;
                    c1 += bias[col + 1] + rv.y;
                } else if (EPI == 3) {
                    const float2 rv = *(const float2*)(res + (size_t)r * N + col);
                    c0 += rv.x;
                    c1 += rv.y;
                }
                *(__half2*)(C + (size_t)r * N + col) = __floats2half2_rn(c0, c1);
            }
        }
    }
}

// ---------------------------------------------------------------------------
// f32 -> fp16 converters (8 floats per thread)
// ---------------------------------------------------------------------------
__global__ __launch_bounds__(256) void cvt_h(
    const float* __restrict__ in, __half* __restrict__ out)
{
    int i = blockIdx.x * blockDim.x + threadIdx.x;     // 8-float chunk index
    float4 v0 = ((const float4*)in)[2 * i];
    float4 v1 = ((const float4*)in)[2 * i + 1];
    ((__half2*)out)[4 * i]     = __floats2half2_rn(v0.x, v0.y);
    ((__half2*)out)[4 * i + 1] = __floats2half2_rn(v0.z, v0.w);
    ((__half2*)out)[4 * i + 2] = __floats2half2_rn(v1.x, v1.y);
    ((__half2*)out)[4 * i + 3] = __floats2half2_rn(v1.z, v1.w);
}

__global__ __launch_bounds__(256) void pack_qkv_h(
    const float* __restrict__ Wq, const float* __restrict__ Wk,
    const float* __restrict__ Wv, __half* __restrict__ Wp)
{
    int i = blockIdx.x * blockDim.x + threadIdx.x;     // 8-float chunk index
    int row = (i * 8) >> 10;
    int col = (i * 8) & 1023;
    const float* src;
    if (row < 1024)      src = Wq + (size_t)row * 1024 + col;
    else if (row < 2048) src = Wk + (size_t)(row - 1024) * 1024 + col;
    else                 src = Wv + (size_t)(row - 2048) * 1024 + col;
    float4 v0 = ((const float4*)src)[0];
    float4 v1 = ((const float4*)src)[1];
    ((__half2*)Wp)[4 * i]     = __floats2half2_rn(v0.x, v0.y);
    ((__half2*)Wp)[4 * i + 1] = __floats2half2_rn(v0.z, v0.w);
    ((__half2*)Wp)[4 * i + 2] = __floats2half2_rn(v1.x, v1.y);
    ((__half2*)Wp)[4 * i + 3] = __floats2half2_rn(v1.z, v1.w);
}

// ---------------------------------------------------------------------------
// FA2-style fp16 flash attention with fp16 mask (R15).
// ---------------------------------------------------------------------------
#define BQ 128
#define HSTR 72
#define Q_BYTES   (BQ * 144)
#define KV_STAGE  (2 * 64 * 144)
#define ATTN_SMEM (Q_BYTES + 2 * KV_STAGE)
#define QKV_SSTRIDE (4*3072)

__global__ __launch_bounds__(256, 2) void attn_reg(
    const __half* __restrict__ qkv, const __half* __restrict__ maskh,
    __half* __restrict__ u)
{
    extern __shared__ __align__(1024) char smc[];
    __half* Qh = (__half*)smc;

    const int n   = blockIdx.y;
    const int bb  = n >> 4;
    const int hh  = n & 15;
    const int s0  = blockIdx.x * BQ;
    const int tid = threadIdx.x;
    const int warp = tid >> 5;
    const int lane = tid & 31;
    const int gr   = lane >> 2;
    const int tig  = lane & 3;
    const int wq   = warp * 16;

    const uint32_t sQ  = saddr(smc);
    const uint32_t sKV = sQ + Q_BYTES;

    const __half* qb = qkv + (size_t)bb * 3072 + hh * 64;
    const __half* kb = qb + 1024;
    const __half* vb = qb + 2048;

#pragma unroll
    for (int it = 0; it < 4; it++) {
        int lin = tid + it * 256;
        int row = lin >> 3;
        int ch  = (lin & 7) * 8;
        uint4 v = *(const uint4*)(qb + (size_t)(s0 + row) * QKV_SSTRIDE + ch);
        *(uint4*)(Qh + row * HSTR + ch) = v;
    }
    __syncthreads();

    uint32_t qf[4][4];
#pragma unroll
    for (int ks = 0; ks < 4; ks++) {
        uint32_t off = (uint32_t)((wq + (lane & 15)) * 144
                                  + ks * 32 + ((lane >> 4) << 4));
        ldsm4(qf[ks][0], qf[ks][1], qf[ks][2], qf[ks][3], sQ + off);
    }
    __syncthreads();

    {
#pragma unroll
        for (int it = 0; it < 4; it++) {
            int lin = tid + it * 256;
            int row = (lin >> 3) & 63;
            int sel = lin >> 9;
            int ch  = lin & 7;
            const __half* src = (sel ? vb : kb) + (size_t)row * QKV_SSTRIDE + ch * 8;
            cp16(sKV + (uint32_t)(sel * 9216 + row * 144 + ch * 16), src);
        }
        asm volatile("cp.async.commit_group;");
    }

    float oacc[8][4];
#pragma unroll
    for (int nt = 0; nt < 8; nt++)
#pragma unroll
        for (int c = 0; c < 4; c++) oacc[nt][c] = 0.f;
    float m0r = -1e30f, m1r = -1e30f;
    float l0r = 0.f,    l1r = 0.f;

    const int NT = SEQ / 64;

    for (int t = 0; t < NT; t++) {
        asm volatile("cp.async.wait_group 0;");
        __syncthreads();

        const uint32_t sK = sKV + (uint32_t)((t & 1) * KV_STAGE);
        const uint32_t sV = sK + 9216u;

        if (t + 1 < NT) {
            const int t0n = (t + 1) * 64;
            const uint32_t dst = sKV + (uint32_t)(((t + 1) & 1) * KV_STAGE);
#pragma unroll
            for (int it = 0; it < 4; it++) {
                int lin = tid + it * 256;
                int row = (lin >> 3) & 63;
                int sel = lin >> 9;
                int ch  = lin & 7;
                const __half* src = (sel ? vb : kb)
                    + (size_t)(t0n + row) * QKV_SSTRIDE + ch * 8;
                cp16(dst + (uint32_t)(sel * 9216 + row * 144 + ch * 16), src);
            }
            asm volatile("cp.async.commit_group;");
        }

        float sacc[8][4];
#pragma unroll
        for (int nt = 0; nt < 8; nt++)
#pragma unroll
            for (int c = 0; c < 4; c++) sacc[nt][c] = 0.f;
#pragma unroll
        for (int ks = 0; ks < 4; ks++) {
#pragma unroll
            for (int np = 0; np < 4; np++) {
                uint32_t b0, b1, b2, b3;
                uint32_t off = (uint32_t)((np * 16 + (lane & 7)
                                           + ((lane >> 4) & 1) * 8) * 144
                                          + ks * 32 + (((lane >> 3) & 1) << 4));
                ldsm4(b0, b1, b2, b3, sK + off);
                mma_f16(sacc[2*np][0], sacc[2*np][1], sacc[2*np][2], sacc[2*np][3],
                        qf[ks][0], qf[ks][1], qf[ks][2], qf[ks][3], b0, b1);
                mma_f16(sacc[2*np+1][0], sacc[2*np+1][1], sacc[2*np+1][2], sacc[2*np+1][3],
                        qf[ks][0], qf[ks][1], qf[ks][2], qf[ks][3], b2, b3);
            }
        }

        const int t0 = t * 64;
        const int r0g = s0 + wq + gr;
#pragma unroll
        for (int nt = 0; nt < 8; nt++) {
            int col = t0 + nt * 8 + 2 * tig;
            const float2 mv0 = __half22float2(
                *(const __half2*)(maskh + (size_t)r0g * SEQ + col));
            const float2 mv1 = __half22float2(
                *(const __half2*)(maskh + (size_t)(r0g + 8) * SEQ + col));
            sacc[nt][0] = (sacc[nt][0] + mv0.x) * 0.125f;
            sacc[nt][1] = (sacc[nt][1] + mv0.y) * 0.125f;
            sacc[nt][2] = (sacc[nt][2] + mv1.x) * 0.125f;
            sacc[nt][3] = (sacc[nt][3] + mv1.y) * 0.125f;
        }

        float tm0 = -1e30f, tm1 = -1e30f;
#pragma unroll
        for (int nt = 0; nt < 8; nt++) {
            tm0 = fmaxf(tm0, fmaxf(sacc[nt][0], sacc[nt][1]));
            tm1 = fmaxf(tm1, fmaxf(sacc[nt][2], sacc[nt][3]));
        }
        tm0 = fmaxf(tm0, __shfl_xor_sync(0xffffffffu, tm0, 1));
        tm0 = fmaxf(tm0, __shfl_xor_sync(0xffffffffu, tm0, 2));
        tm1 = fmaxf(tm1, __shfl_xor_sync(0xffffffffu, tm1, 1));
        tm1 = fmaxf(tm1, __shfl_xor_sync(0xffffffffu, tm1, 2));

        float nm0 = fmaxf(m0r, tm0);
        float nm1 = fmaxf(m1r, tm1);
        float cr0 = __expf(m0r - nm0);
        float cr1 = __expf(m1r - nm1);
        m0r = nm0; m1r = nm1;

        uint32_t pf[4][4];
        float sum0 = 0.f, sum1 = 0.f;
#pragma unroll
        for (int j = 0; j < 4; j++) {
            float e00 = __expf(sacc[2*j][0] - nm0);
            float e01 = __expf(sacc[2*j][1] - nm0);
            float e02 = __expf(sacc[2*j][2] - nm1);
            float e03 = __expf(sacc[2*j][3] - nm1);
            float e10 = __expf(sacc[2*j+1][0] - nm0);
            float e11 = __expf(sacc[2*j+1][1] - nm0);
            float e12 = __expf(sacc[2*j+1][2] - nm1);
            float e13 = __expf(sacc[2*j+1][3] - nm1);
            sum0 += e00 + e01 + e10 + e11;
            sum1 += e02 + e03 + e12 + e13;
            pf[j][0] = h2u(__floats2half2_rn(e00, e01));
            pf[j][1] = h2u(__floats2half2_rn(e02, e03));
            pf[j][2] = h2u(__floats2half2_rn(e10, e11));
            pf[j][3] = h2u(__floats2half2_rn(e12, e13));
        }
        sum0 += __shfl_xor_sync(0xffffffffu, sum0, 1);
        sum0 += __shfl_xor_sync(0xffffffffu, sum0, 2);
        sum1 += __shfl_xor_sync(0xffffffffu, sum1, 1);
        sum1 += __shfl_xor_sync(0xffffffffu, sum1, 2);
        l0r = l0r * cr0 + sum0;
        l1r = l1r * cr1 + sum1;

#pragma unroll
        for (int nt = 0; nt < 8; nt++) {
            oacc[nt][0] *= cr0; oacc[nt][1] *= cr0;
            oacc[nt][2] *= cr1; oacc[nt][3] *= cr1;
        }
#pragma unroll
        for (int ks = 0; ks < 4; ks++) {
#pragma unroll
            for (int np = 0; np < 4; np++) {
                uint32_t b0, b1, b2, b3;
                int vrow = ks * 16 + (lane & 7) + ((lane >> 3) & 1) * 8;
                int vcol = np * 16 + ((lane >> 4) & 1) * 8;
                ldsm4_t(b0, b1, b2, b3, sV + (uint32_t)(vrow * 144 + vcol * 2));
                mma_f16(oacc[2*np][0], oacc[2*np][1], oacc[2*np][2], oacc[2*np][3],
                        pf[ks][0], pf[ks][1], pf[ks][2], pf[ks][3], b0, b1);
                mma_f16(oacc[2*np+1][0], oacc[2*np+1][1], oacc[2*np+1][2], oacc[2*np+1][3],
                        pf[ks][0], pf[ks][1], pf[ks][2], pf[ks][3], b2, b3);
            }
        }
    }

    {
        float inv0 = 1.f / l0r;
        float inv1 = 1.f / l1r;
        const int r0g = s0 + wq + gr;
#pragma unroll
        for (int nt = 0; nt < 8; nt++) {
            int col = nt * 8 + 2 * tig;
            *(__half2*)(u + (size_t)r0g * 4096 + (size_t)n * 64 + col) =
                __floats2half2_rn(oacc[nt][0] * inv0, oacc[nt][1] * inv0);
            *(__half2*)(u + (size_t)(r0g + 8) * 4096 + (size_t)n * 64 + col) =
                __floats2half2_rn(oacc[nt][2] * inv1, oacc[nt][3] * inv1);
        }
    }
}

// ---------------------------------------------------------------------------
// LayerNorm over last dim (1024), fp16 input; f32 output + optional fp16.
// ---------------------------------------------------------------------------
__global__ __launch_bounds__(256) void ln_h(
    const __half* __restrict__ in, const float* __restrict__ g,
    const float* __restrict__ be, float* __restrict__ out,
    __half* __restrict__ outh)
{
    const int row = blockIdx.x;
    const int tid = threadIdx.x;
    __shared__ float red[8];
    __shared__ float s_mu, s_rstd;

    uint2 raw = *(const uint2*)(in + (size_t)row * DMODEL + tid * 4);
    float2 f0 = __half22float2(((const __half2*)&raw)[0]);
    float2 f1 = __half22float2(((const __half2*)&raw)[1]);
    float4 v; v.x = f0.x; v.y = f0.y; v.z = f1.x; v.w = f1.y;

    float s = v.x + v.y + v.z + v.w;
#pragma unroll
    for (int o = 16; o > 0; o >>= 1) s += __shfl_xor_sync(0xffffffffu, s, o);
    if ((tid & 31) == 0) red[tid >> 5] = s;
    __syncthreads();
    if (tid < 8) {
        float t = red[tid];
#pragma unroll
        for (int o = 4; o > 0; o >>= 1) t += __shfl_xor_sync(0xffu, t, o);
        if (tid == 0) s_mu = t * (1.f / DMODEL);
    }
    __syncthreads();
    float mu = s_mu;
    float d0 = v.x - mu, d1 = v.y - mu, d2 = v.z - mu, d3 = v.w - mu;
    float s2 = d0 * d0 + d1 * d1 + d2 * d2 + d3 * d3;
#pragma unroll
    for (int o = 16; o > 0; o >>= 1) s2 += __shfl_xor_sync(0xffffffffu, s2, o);
    if ((tid & 31) == 0) red[tid >> 5] = s2;
    __syncthreads();
    if (tid < 8) {
        float t = red[tid];
#pragma unroll
        for (int o = 4; o > 0; o >>= 1) t += __shfl_xor_sync(0xffu, t, o);
        if (tid == 0) s_rstd = rsqrtf(t * (1.f / DMODEL) + LN_EPS);
    }
    __syncthreads();
    float rstd = s_rstd;
    float4 gv = *(const float4*)(g + tid * 4);
    float4 bv = *(const float4*)(be + tid * 4);
    float4 ov;
    ov.x = d0 * rstd * gv.x + bv.x;
    ov.y = d1 * rstd * gv.y + bv.y;
    ov.z = d2 * rstd * gv.z + bv.z;
    ov.w = d3 * rstd * gv.w + bv.w;
    *(float4*)(out + (size_t)row * DMODEL + tid * 4) = ov;
    if (outh != nullptr) {
        *(__half2*)(outh + (size_t)row * DMODEL + tid * 4)     = __floats2half2_rn(ov.x, ov.y);
        *(__half2*)(outh + (size_t)row * DMODEL + tid * 4 + 2) = __floats2half2_rn(ov.z, ov.w);
    }
}

// ---------------------------------------------------------------------------
extern "C" void kernel_launch(void* const* d_in, const int* in_sizes, int n_in,
                              void* d_out, int out_size)
{
    const float* x    = (const float*)d_in[0];
    const float* mask = (const float*)d_in[1];
    const float* Wq   = (const float*)d_in[2];
    const float* Wk   = (const float*)d_in[3];
    const float* Wv   = (const float*)d_in[4];
    const float* Wc   = (const float*)d_in[5];
    const float* W1   = (const float*)d_in[6];
    const float* b1   = (const float*)d_in[7];
    const float* W2   = (const float*)d_in[8];
    const float* b2   = (const float*)d_in[9];
    const float* g1   = (const float*)d_in[10];
    const float* be1  = (const float*)d_in[11];
    const float* g2   = (const float*)d_in[12];
    const float* be2  = (const float*)d_in[13];
    float* out = (float*)d_out;

    __half *xh, *wph, *wch, *w1h, *w2h, *maskh, *qkvh, *uh, *t1h, *t2h, *t3h, *hidh;
    float *t2;
    cudaGetSymbolAddress((void**)&xh,    g_xh);
    cudaGetSymbolAddress((void**)&wph,   g_wph);
    cudaGetSymbolAddress((void**)&wch,   g_wch);
    cudaGetSymbolAddress((void**)&w1h,   g_w1h);
    cudaGetSymbolAddress((void**)&w2h,   g_w2h);
    cudaGetSymbolAddress((void**)&maskh, g_maskh);
    cudaGetSymbolAddress((void**)&qkvh,  g_qkvh);
    cudaGetSymbolAddress((void**)&uh,    g_uh);
    cudaGetSymbolAddress((void**)&t1h,   g_t1h);
    cudaGetSymbolAddress((void**)&t2h,   g_t2h);
    cudaGetSymbolAddress((void**)&t3h,   g_t3h);
    cudaGetSymbolAddress((void**)&hidh,  g_hidh);
    cudaGetSymbolAddress((void**)&t2,    g_t2);

    cudaFuncSetAttribute(attn_reg, cudaFuncAttributeMaxDynamicSharedMemorySize, ATTN_SMEM);
    cudaFuncSetAttribute(gemm_h, cudaFuncAttributeMaxDynamicSharedMemorySize, GEMM_SMEM_BYTES);

    dim3 blk(256);

    // fp16 conversions (8 floats/thread)
    cvt_h<<<(MROWS * DMODEL / 8) / 256, blk>>>(x, xh);
    pack_qkv_h<<<(3072 * DMODEL / 8) / 256, blk>>>(Wq, Wk, Wv, wph);
    cvt_h<<<(DMODEL * DMODEL / 8) / 256, blk>>>(Wc, wch);
    cvt_h<<<(FFDIM * DMODEL / 8) / 256, blk>>>(W1, w1h);
    cvt_h<<<(DMODEL * FFDIM / 8) / 256, blk>>>(W2, w2h);
    cvt_h<<<(SEQ * SEQ / 8) / 256, blk>>>(mask, maskh);

    // fused QKV projection -> qkvh fp16 [8192, 3072]
    gemm_h<<<dim3(3072 / 128, MROWS / 128), blk, GEMM_SMEM_BYTES>>>(
        xh, wph, nullptr, nullptr, qkvh, 3072, DMODEL, 0);

    // attention -> uh fp16
    attn_reg<<<dim3(SEQ / BQ, 64), blk, ATTN_SMEM>>>(qkvh, maskh, uh);

    // x + u @ Wc^T -> t1h fp16;  LN1 -> t2 f32 + t2h fp16
    gemm_h<<<dim3(DMODEL / 128, MROWS / 128), blk, GEMM_SMEM_BYTES>>>(
        uh, wch, nullptr, x, t1h, DMODEL, DMODEL, 3);
    ln_h<<<MROWS, blk>>>(t1h, g1, be1, t2, t2h);

    // FFN: relu(t2h@W1^T+b1) -> hidh;  hid@W2^T+b2 + t2 -> t3h;  LN2 -> out
    gemm_h<<<dim3(FFDIM / 128, MROWS / 128), blk, GEMM_SMEM_BYTES>>>(
        t2h, w1h, b1, nullptr, hidh, FFDIM, DMODEL, 1);
    gemm_h<<<dim3(DMODEL / 128, MROWS / 128), blk, GEMM_SMEM_BYTES>>>(
        hidh, w2h, b2, t2, t3h, DMODEL, FFDIM, 2);
    ln_h<<<MROWS, blk>>>(t3h, g2, be2, out, nullptr);
}

// round 17
// speedup vs baseline: 1.0571x; 1.0006x over previous
#include <cuda_runtime.h>
#include <cuda_fp16.h>
#include <math.h>
#include <stdint.h>

// ---------------------------------------------------------------------------
// PTransformerBlock: S=2048 B=4 D=1024 H=16 K=64 FF=4096.
// Round 17: all-fp16 residual path (EPI residual reads fp16, LN1 writes
//           fp16 only, f32 t2 buffer deleted). GEMM/attention at R16 best.
// ---------------------------------------------------------------------------

#define SEQ   2048
#define BATCH 4
#define DMODEL 1024
#define FFDIM 4096
#define MROWS (SEQ*BATCH)   // 8192
#define LN_EPS 1e-5f

// scratch (allocation-free: device globals)
__device__ __half g_xh   [MROWS * DMODEL];
__device__ __half g_wph  [3072 * DMODEL];
__device__ __half g_wch  [DMODEL * DMODEL];
__device__ __half g_w1h  [FFDIM * DMODEL];
__device__ __half g_w2h  [DMODEL * FFDIM];
__device__ __half g_maskh[SEQ * SEQ];
__device__ __half g_qkvh [MROWS * 3072];
__device__ __half g_uh   [MROWS * DMODEL];
__device__ __half g_t1h  [MROWS * DMODEL];
__device__ __half g_t2h  [MROWS * DMODEL];
__device__ __half g_t3h  [MROWS * DMODEL];
__device__ __half g_hidh [MROWS * FFDIM];

__device__ __forceinline__ uint32_t h2u(__half2 h) {
    union { __half2 h; uint32_t u; } c;
    c.h = h;
    return c.u;
}

__device__ __forceinline__ void mma_f16(
    float& d0, float& d1, float& d2, float& d3,
    uint32_t a0, uint32_t a1, uint32_t a2, uint32_t a3,
    uint32_t b0, uint32_t b1)
{
    asm volatile(
        "mma.sync.aligned.m16n8k16.row.col.f32.f16.f16.f32 "
        "{%0,%1,%2,%3}, {%4,%5,%6,%7}, {%8,%9}, {%0,%1,%2,%3};"
        : "+f"(d0), "+f"(d1), "+f"(d2), "+f"(d3)
        : "r"(a0), "r"(a1), "r"(a2), "r"(a3), "r"(b0), "r"(b1));
}

__device__ __forceinline__ void ldsm4(
    uint32_t& r0, uint32_t& r1, uint32_t& r2, uint32_t& r3, uint32_t addr)
{
    asm volatile("ldmatrix.sync.aligned.m8n8.x4.shared.b16 {%0,%1,%2,%3}, [%4];"
                 : "=r"(r0), "=r"(r1), "=r"(r2), "=r"(r3) : "r"(addr));
}
__device__ __forceinline__ void ldsm4_t(
    uint32_t& r0, uint32_t& r1, uint32_t& r2, uint32_t& r3, uint32_t addr)
{
    asm volatile("ldmatrix.sync.aligned.m8n8.x4.trans.shared.b16 {%0,%1,%2,%3}, [%4];"
                 : "=r"(r0), "=r"(r1), "=r"(r2), "=r"(r3) : "r"(addr));
}

__device__ __forceinline__ void cp16(uint32_t s, const void* g) {
    asm volatile("cp.async.cg.shared.global [%0], [%1], 16;" :: "r"(s), "l"(g));
}
__device__ __forceinline__ uint32_t saddr(const void* p) {
    return (uint32_t)__cvta_generic_to_shared(p);
}
#define SWZ128(o) ((o) ^ (((o) >> 3) & 0x70))

// ---------------------------------------------------------------------------
// fp16 tensor-core GEMM (R13 config).
// EPI: 0=none  1=+bias,relu  2=+bias,+res(fp16)  3=+res(fp16)   out fp16 all
// ---------------------------------------------------------------------------
#define STAGE_BYTES 32768
#define NSTAGE 3
#define GEMM_SMEM_BYTES (NSTAGE * STAGE_BYTES)

__device__ __forceinline__ void load_tile_h(
    uint32_t base, const __half* __restrict__ A, const __half* __restrict__ W,
    int m0, int n0, int Kd, int k0, int tid)
{
#pragma unroll
    for (int it = 0; it < 4; it++) {
        int lin = tid + it * 256;
        int row = lin >> 3;
        int ch  = lin & 7;
        uint32_t off = (uint32_t)(row * 128 + ch * 16);
        uint32_t sw  = SWZ128(off);
        cp16(base + sw,         A + (size_t)(m0 + row) * Kd + k0 + ch * 8);
        cp16(base + 16384 + sw, W + (size_t)(n0 + row) * Kd + k0 + ch * 8);
    }
}

__global__ __launch_bounds__(256, 2) void gemm_h(
    const __half* __restrict__ A, const __half* __restrict__ W,
    const float* __restrict__ bias, const __half* __restrict__ res,
    __half* __restrict__ C, int N, int Kd, int EPI)
{
    extern __shared__ __align__(1024) char smem[];

    const int tid  = threadIdx.x;
    const int warp = tid >> 5;
    const int lane = tid & 31;
    const int gr   = lane >> 2;
    const int tig  = lane & 3;
    const int wm   = (warp & 1) * 64;
    const int wn   = (warp >> 1) * 32;
    const int m0   = blockIdx.y * 128;
    const int n0   = blockIdx.x * 128;

    const uint32_t sb = saddr(smem);

    float acc[4][4][4];
#pragma unroll
    for (int mt = 0; mt < 4; mt++)
#pragma unroll
        for (int nt = 0; nt < 4; nt++)
#pragma unroll
            for (int c = 0; c < 4; c++) acc[mt][nt][c] = 0.f;

    const int ktiles = Kd >> 6;

#pragma unroll
    for (int pf = 0; pf < 2; pf++) {
        load_tile_h(sb + pf * STAGE_BYTES, A, W, m0, n0, Kd, pf * 64, tid);
        asm volatile("cp.async.commit_group;");
    }

    for (int t = 0; t < ktiles; t++) {
        if (t + 1 < ktiles) asm volatile("cp.async.wait_group 1;");
        else                asm volatile("cp.async.wait_group 0;");
        __syncthreads();

        if (t + 2 < ktiles) {
            load_tile_h(sb + (uint32_t)(((t + 2) % NSTAGE) * STAGE_BYTES),
                        A, W, m0, n0, Kd, (t + 2) * 64, tid);
            asm volatile("cp.async.commit_group;");
        }

        const uint32_t sA = sb + (uint32_t)((t % NSTAGE) * STAGE_BYTES);
        const uint32_t sB = sA + 16384u;

#pragma unroll
        for (int ks = 0; ks < 4; ks++) {
            uint32_t a[4][4], b[4][2];
#pragma unroll
            for (int mt = 0; mt < 4; mt++) {
                uint32_t off = (uint32_t)((wm + mt * 16 + (lane & 15)) * 128
                                          + ks * 32 + ((lane >> 4) << 4));
                ldsm4(a[mt][0], a[mt][1], a[mt][2], a[mt][3], sA + SWZ128(off));
            }
#pragma unroll
            for (int np = 0; np < 2; np++) {
                uint32_t off = (uint32_t)((wn + np * 16 + (lane & 7)
                                           + ((lane >> 4) & 1) * 8) * 128
                                          + ks * 32 + (((lane >> 3) & 1) << 4));
                ldsm4(b[2 * np][0], b[2 * np][1], b[2 * np + 1][0], b[2 * np + 1][1],
                      sB + SWZ128(off));
            }
#pragma unroll
            for (int mt = 0; mt < 4; mt++)
#pragma unroll
                for (int nt = 0; nt < 4; nt++)
                    mma_f16(acc[mt][nt][0], acc[mt][nt][1], acc[mt][nt][2], acc[mt][nt][3],
                            a[mt][0], a[mt][1], a[mt][2], a[mt][3],
                            b[nt][0], b[nt][1]);
        }
    }

#pragma unroll
    for (int mt = 0; mt < 4; mt++) {
#pragma unroll
        for (int nt = 0; nt < 4; nt++) {
            int row = m0 + wm + mt * 16 + gr;
            int col = n0 + wn + nt * 8 + 2 * tig;
#pragma unroll
            for (int h = 0; h < 2; h++) {
                int r = row + h * 8;
                float c0 = acc[mt][nt][h * 2 + 0];
                float c1 = acc[mt][nt][h * 2 + 1];
                if (EPI == 1) {
                    c0 = fmaxf(c0 + bias[col], 0.f);
                    c1 = fmaxf(c1 + bias[col + 1], 0.f);
                } else if (EPI == 2) {
                    const float2 rv = __half22float2(
                        *(const __half2*)(res + (size_t)r * N + col));
                    c0 += bias[col] + rv.x;
                    c1 += bias[col + 1] + rv.y;
                } else if (EPI == 3) {
                    const float2 rv = __half22float2(
                        *(const __half2*)(res + (size_t)r * N + col));
                    c0 += rv.x;
                    c1 += rv.y;
                }
                *(__half2*)(C + (size_t)r * N + col) = __floats2half2_rn(c0, c1);
            }
        }
    }
}

// ---------------------------------------------------------------------------
// f32 -> fp16 converters (8 floats per thread)
// ---------------------------------------------------------------------------
__global__ __launch_bounds__(256) void cvt_h(
    const float* __restrict__ in, __half* __restrict__ out)
{
    int i = blockIdx.x * blockDim.x + threadIdx.x;
    float4 v0 = ((const float4*)in)[2 * i];
    float4 v1 = ((const float4*)in)[2 * i + 1];
    ((__half2*)out)[4 * i]     = __floats2half2_rn(v0.x, v0.y);
    ((__half2*)out)[4 * i + 1] = __floats2half2_rn(v0.z, v0.w);
    ((__half2*)out)[4 * i + 2] = __floats2half2_rn(v1.x, v1.y);
    ((__half2*)out)[4 * i + 3] = __floats2half2_rn(v1.z, v1.w);
}

__global__ __launch_bounds__(256) void pack_qkv_h(
    const float* __restrict__ Wq, const float* __restrict__ Wk,
    const float* __restrict__ Wv, __half* __restrict__ Wp)
{
    int i = blockIdx.x * blockDim.x + threadIdx.x;
    int row = (i * 8) >> 10;
    int col = (i * 8) & 1023;
    const float* src;
    if (row < 1024)      src = Wq + (size_t)row * 1024 + col;
    else if (row < 2048) src = Wk + (size_t)(row - 1024) * 1024 + col;
    else                 src = Wv + (size_t)(row - 2048) * 1024 + col;
    float4 v0 = ((const float4*)src)[0];
    float4 v1 = ((const float4*)src)[1];
    ((__half2*)Wp)[4 * i]     = __floats2half2_rn(v0.x, v0.y);
    ((__half2*)Wp)[4 * i + 1] = __floats2half2_rn(v0.z, v0.w);
    ((__half2*)Wp)[4 * i + 2] = __floats2half2_rn(v1.x, v1.y);
    ((__half2*)Wp)[4 * i + 3] = __floats2half2_rn(v1.z, v1.w);
}

// ---------------------------------------------------------------------------
// FA2-style fp16 flash attention with fp16 mask (R15/R16).
// ---------------------------------------------------------------------------
#define BQ 128
#define HSTR 72
#define Q_BYTES   (BQ * 144)
#define KV_STAGE  (2 * 64 * 144)
#define ATTN_SMEM (Q_BYTES + 2 * KV_STAGE)
#define QKV_SSTRIDE (4*3072)

__global__ __launch_bounds__(256, 2) void attn_reg(
    const __half* __restrict__ qkv, const __half* __restrict__ maskh,
    __half* __restrict__ u)
{
    extern __shared__ __align__(1024) char smc[];
    __half* Qh = (__half*)smc;

    const int n   = blockIdx.y;
    const int bb  = n >> 4;
    const int hh  = n & 15;
    const int s0  = blockIdx.x * BQ;
    const int tid = threadIdx.x;
    const int warp = tid >> 5;
    const int lane = tid & 31;
    const int gr   = lane >> 2;
    const int tig  = lane & 3;
    const int wq   = warp * 16;

    const uint32_t sQ  = saddr(smc);
    const uint32_t sKV = sQ + Q_BYTES;

    const __half* qb = qkv + (size_t)bb * 3072 + hh * 64;
    const __half* kb = qb + 1024;
    const __half* vb = qb + 2048;

#pragma unroll
    for (int it = 0; it < 4; it++) {
        int lin = tid + it * 256;
        int row = lin >> 3;
        int ch  = (lin & 7) * 8;
        uint4 v = *(const uint4*)(qb + (size_t)(s0 + row) * QKV_SSTRIDE + ch);
        *(uint4*)(Qh + row * HSTR + ch) = v;
    }
    __syncthreads();

    uint32_t qf[4][4];
#pragma unroll
    for (int ks = 0; ks < 4; ks++) {
        uint32_t off = (uint32_t)((wq + (lane & 15)) * 144
                                  + ks * 32 + ((lane >> 4) << 4));
        ldsm4(qf[ks][0], qf[ks][1], qf[ks][2], qf[ks][3], sQ + off);
    }
    __syncthreads();

    {
#pragma unroll
        for (int it = 0; it < 4; it++) {
            int lin = tid + it * 256;
            int row = (lin >> 3) & 63;
            int sel = lin >> 9;
            int ch  = lin & 7;
            const __half* src = (sel ? vb : kb) + (size_t)row * QKV_SSTRIDE + ch * 8;
            cp16(sKV + (uint32_t)(sel * 9216 + row * 144 + ch * 16), src);
        }
        asm volatile("cp.async.commit_group;");
    }

    float oacc[8][4];
#pragma unroll
    for (int nt = 0; nt < 8; nt++)
#pragma unroll
        for (int c = 0; c < 4; c++) oacc[nt][c] = 0.f;
    float m0r = -1e30f, m1r = -1e30f;
    float l0r = 0.f,    l1r = 0.f;

    const int NT = SEQ / 64;

    for (int t = 0; t < NT; t++) {
        asm volatile("cp.async.wait_group 0;");
        __syncthreads();

        const uint32_t sK = sKV + (uint32_t)((t & 1) * KV_STAGE);
        const uint32_t sV = sK + 9216u;

        if (t + 1 < NT) {
            const int t0n = (t + 1) * 64;
            const uint32_t dst = sKV + (uint32_t)(((t + 1) & 1) * KV_STAGE);
#pragma unroll
            for (int it = 0; it < 4; it++) {
                int lin = tid + it * 256;
                int row = (lin >> 3) & 63;
                int sel = lin >> 9;
                int ch  = lin & 7;
                const __half* src = (sel ? vb : kb)
                    + (size_t)(t0n + row) * QKV_SSTRIDE + ch * 8;
                cp16(dst + (uint32_t)(sel * 9216 + row * 144 + ch * 16), src);
            }
            asm volatile("cp.async.commit_group;");
        }

        float sacc[8][4];
#pragma unroll
        for (int nt = 0; nt < 8; nt++)
#pragma unroll
            for (int c = 0; c < 4; c++) sacc[nt][c] = 0.f;
#pragma unroll
        for (int ks = 0; ks < 4; ks++) {
#pragma unroll
            for (int np = 0; np < 4; np++) {
                uint32_t b0, b1, b2, b3;
                uint32_t off = (uint32_t)((np * 16 + (lane & 7)
                                           + ((lane >> 4) & 1) * 8) * 144
                                          + ks * 32 + (((lane >> 3) & 1) << 4));
                ldsm4(b0, b1, b2, b3, sK + off);
                mma_f16(sacc[2*np][0], sacc[2*np][1], sacc[2*np][2], sacc[2*np][3],
                        qf[ks][0], qf[ks][1], qf[ks][2], qf[ks][3], b0, b1);
                mma_f16(sacc[2*np+1][0], sacc[2*np+1][1], sacc[2*np+1][2], sacc[2*np+1][3],
                        qf[ks][0], qf[ks][1], qf[ks][2], qf[ks][3], b2, b3);
            }
        }

        const int t0 = t * 64;
        const int r0g = s0 + wq + gr;
#pragma unroll
        for (int nt = 0; nt < 8; nt++) {
            int col = t0 + nt * 8 + 2 * tig;
            const float2 mv0 = __half22float2(
                *(const __half2*)(maskh + (size_t)r0g * SEQ + col));
            const float2 mv1 = __half22float2(
                *(const __half2*)(maskh + (size_t)(r0g + 8) * SEQ + col));
            sacc[nt][0] = (sacc[nt][0] + mv0.x) * 0.125f;
            sacc[nt][1] = (sacc[nt][1] + mv0.y) * 0.125f;
            sacc[nt][2] = (sacc[nt][2] + mv1.x) * 0.125f;
            sacc[nt][3] = (sacc[nt][3] + mv1.y) * 0.125f;
        }

        float tm0 = -1e30f, tm1 = -1e30f;
#pragma unroll
        for (int nt = 0; nt < 8; nt++) {
            tm0 = fmaxf(tm0, fmaxf(sacc[nt][0], sacc[nt][1]));
            tm1 = fmaxf(tm1, fmaxf(sacc[nt][2], sacc[nt][3]));
        }
        tm0 = fmaxf(tm0, __shfl_xor_sync(0xffffffffu, tm0, 1));
        tm0 = fmaxf(tm0, __shfl_xor_sync(0xffffffffu, tm0, 2));
        tm1 = fmaxf(tm1, __shfl_xor_sync(0xffffffffu, tm1, 1));
        tm1 = fmaxf(tm1, __shfl_xor_sync(0xffffffffu, tm1, 2));

        float nm0 = fmaxf(m0r, tm0);
        float nm1 = fmaxf(m1r, tm1);
        float cr0 = __expf(m0r - nm0);
        float cr1 = __expf(m1r - nm1);
        m0r = nm0; m1r = nm1;

        uint32_t pf[4][4];
        float sum0 = 0.f, sum1 = 0.f;
#pragma unroll
        for (int j = 0; j < 4; j++) {
            float e00 = __expf(sacc[2*j][0] - nm0);
            float e01 = __expf(sacc[2*j][1] - nm0);
            float e02 = __expf(sacc[2*j][2] - nm1);
            float e03 = __expf(sacc[2*j][3] - nm1);
            float e10 = __expf(sacc[2*j+1][0] - nm0);
            float e11 = __expf(sacc[2*j+1][1] - nm0);
            float e12 = __expf(sacc[2*j+1][2] - nm1);
            float e13 = __expf(sacc[2*j+1][3] - nm1);
            sum0 += e00 + e01 + e10 + e11;
            sum1 += e02 + e03 + e12 + e13;
            pf[j][0] = h2u(__floats2half2_rn(e00, e01));
            pf[j][1] = h2u(__floats2half2_rn(e02, e03));
            pf[j][2] = h2u(__floats2half2_rn(e10, e11));
            pf[j][3] = h2u(__floats2half2_rn(e12, e13));
        }
        sum0 += __shfl_xor_sync(0xffffffffu, sum0, 1);
        sum0 += __shfl_xor_sync(0xffffffffu, sum0, 2);
        sum1 += __shfl_xor_sync(0xffffffffu, sum1, 1);
        sum1 += __shfl_xor_sync(0xffffffffu, sum1, 2);
        l0r = l0r * cr0 + sum0;
        l1r = l1r * cr1 + sum1;

#pragma unroll
        for (int nt = 0; nt < 8; nt++) {
            oacc[nt][0] *= cr0; oacc[nt][1] *= cr0;
            oacc[nt][2] *= cr1; oacc[nt][3] *= cr1;
        }
#pragma unroll
        for (int ks = 0; ks < 4; ks++) {
#pragma unroll
            for (int np = 0; np < 4; np++) {
                uint32_t b0, b1, b2, b3;
                int vrow = ks * 16 + (lane & 7) + ((lane >> 3) & 1) * 8;
                int vcol = np * 16 + ((lane >> 4) & 1) * 8;
                ldsm4_t(b0, b1, b2, b3, sV + (uint32_t)(vrow * 144 + vcol * 2));
                mma_f16(oacc[2*np][0], oacc[2*np][1], oacc[2*np][2], oacc[2*np][3],
                        pf[ks][0], pf[ks][1], pf[ks][2], pf[ks][3], b0, b1);
                mma_f16(oacc[2*np+1][0], oacc[2*np+1][1], oacc[2*np+1][2], oacc[2*np+1][3],
                        pf[ks][0], pf[ks][1], pf[ks][2], pf[ks][3], b2, b3);
            }
        }
    }

    {
        float inv0 = 1.f / l0r;
        float inv1 = 1.f / l1r;
        const int r0g = s0 + wq + gr;
#pragma unroll
        for (int nt = 0; nt < 8; nt++) {
            int col = nt * 8 + 2 * tig;
            *(__half2*)(u + (size_t)r0g * 4096 + (size_t)n * 64 + col) =
                __floats2half2_rn(oacc[nt][0] * inv0, oacc[nt][1] * inv0);
            *(__half2*)(u + (size_t)(r0g + 8) * 4096 + (size_t)n * 64 + col) =
                __floats2half2_rn(oacc[nt][2] * inv1, oacc[nt][3] * inv1);
        }
    }
}

// ---------------------------------------------------------------------------
// LayerNorm over last dim (1024), fp16 input; optional f32 / fp16 outputs.
// ---------------------------------------------------------------------------
__global__ __launch_bounds__(256) void ln_h(
    const __half* __restrict__ in, const float* __restrict__ g,
    const float* __restrict__ be, float* __restrict__ out,
    __half* __restrict__ outh)
{
    const int row = blockIdx.x;
    const int tid = threadIdx.x;
    __shared__ float red[8];
    __shared__ float s_mu, s_rstd;

    uint2 raw = *(const uint2*)(in + (size_t)row * DMODEL + tid * 4);
    float2 f0 = __half22float2(((const __half2*)&raw)[0]);
    float2 f1 = __half22float2(((const __half2*)&raw)[1]);
    float4 v; v.x = f0.x; v.y = f0.y; v.z = f1.x; v.w = f1.y;

    float s = v.x + v.y + v.z + v.w;
#pragma unroll
    for (int o = 16; o > 0; o >>= 1) s += __shfl_xor_sync(0xffffffffu, s, o);
    if ((tid & 31) == 0) red[tid >> 5] = s;
    __syncthreads();
    if (tid < 8) {
        float t = red[tid];
#pragma unroll
        for (int o = 4; o > 0; o >>= 1) t += __shfl_xor_sync(0xffu, t, o);
        if (tid == 0) s_mu = t * (1.f / DMODEL);
    }
    __syncthreads();
    float mu = s_mu;
    float d0 = v.x - mu, d1 = v.y - mu, d2 = v.z - mu, d3 = v.w - mu;
    float s2 = d0 * d0 + d1 * d1 + d2 * d2 + d3 * d3;
#pragma unroll
    for (int o = 16; o > 0; o >>= 1) s2 += __shfl_xor_sync(0xffffffffu, s2, o);
    if ((tid & 31) == 0) red[tid >> 5] = s2;
    __syncthreads();
    if (tid < 8) {
        float t = red[tid];
#pragma unroll
        for (int o = 4; o > 0; o >>= 1) t += __shfl_xor_sync(0xffu, t, o);
        if (tid == 0) s_rstd = rsqrtf(t * (1.f / DMODEL) + LN_EPS);
    }
    __syncthreads();
    float rstd = s_rstd;
    float4 gv = *(const float4*)(g + tid * 4);
    float4 bv = *(const float4*)(be + tid * 4);
    float4 ov;
    ov.x = d0 * rstd * gv.x + bv.x;
    ov.y = d1 * rstd * gv.y + bv.y;
    ov.z = d2 * rstd * gv.z + bv.z;
    ov.w = d3 * rstd * gv.w + bv.w;
    if (out != nullptr)
        *(float4*)(out + (size_t)row * DMODEL + tid * 4) = ov;
    if (outh != nullptr) {
        *(__half2*)(outh + (size_t)row * DMODEL + tid * 4)     = __floats2half2_rn(ov.x, ov.y);
        *(__half2*)(outh + (size_t)row * DMODEL + tid * 4 + 2) = __floats2half2_rn(ov.z, ov.w);
    }
}

// ---------------------------------------------------------------------------
extern "C" void kernel_launch(void* const* d_in, const int* in_sizes, int n_in,
                              void* d_out, int out_size)
{
    const float* x    = (const float*)d_in[0];
    const float* mask = (const float*)d_in[1];
    const float* Wq   = (const float*)d_in[2];
    const float* Wk   = (const float*)d_in[3];
    const float* Wv   = (const float*)d_in[4];
    const float* Wc   = (const float*)d_in[5];
    const float* W1   = (const float*)d_in[6];
    const float* b1   = (const float*)d_in[7];
    const float* W2   = (const float*)d_in[8];
    const float* b2   = (const float*)d_in[9];
    const float* g1   = (const float*)d_in[10];
    const float* be1  = (const float*)d_in[11];
    const float* g2   = (const float*)d_in[12];
    const float* be2  = (const float*)d_in[13];
    float* out = (float*)d_out;

    __half *xh, *wph, *wch, *w1h, *w2h, *maskh, *qkvh, *uh, *t1h, *t2h, *t3h, *hidh;
    cudaGetSymbolAddress((void**)&xh,    g_xh);
    cudaGetSymbolAddress((void**)&wph,   g_wph);
    cudaGetSymbolAddress((void**)&wch,   g_wch);
    cudaGetSymbolAddress((void**)&w1h,   g_w1h);
    cudaGetSymbolAddress((void**)&w2h,   g_w2h);
    cudaGetSymbolAddress((void**)&maskh, g_maskh);
    cudaGetSymbolAddress((void**)&qkvh,  g_qkvh);
    cudaGetSymbolAddress((void**)&uh,    g_uh);
    cudaGetSymbolAddress((void**)&t1h,   g_t1h);
    cudaGetSymbolAddress((void**)&t2h,   g_t2h);
    cudaGetSymbolAddress((void**)&t3h,   g_t3h);
    cudaGetSymbolAddress((void**)&hidh,  g_hidh);

    cudaFuncSetAttribute(attn_reg, cudaFuncAttributeMaxDynamicSharedMemorySize, ATTN_SMEM);
    cudaFuncSetAttribute(gemm_h, cudaFuncAttributeMaxDynamicSharedMemorySize, GEMM_SMEM_BYTES);

    dim3 blk(256);

    // fp16 conversions (8 floats/thread)
    cvt_h<<<(MROWS * DMODEL / 8) / 256, blk>>>(x, xh);
    pack_qkv_h<<<(3072 * DMODEL / 8) / 256, blk>>>(Wq, Wk, Wv, wph);
    cvt_h<<<(DMODEL * DMODEL / 8) / 256, blk>>>(Wc, wch);
    cvt_h<<<(FFDIM * DMODEL / 8) / 256, blk>>>(W1, w1h);
    cvt_h<<<(DMODEL * FFDIM / 8) / 256, blk>>>(W2, w2h);
    cvt_h<<<(SEQ * SEQ / 8) / 256, blk>>>(mask, maskh);

    // fused QKV projection -> qkvh fp16 [8192, 3072]
    gemm_h<<<dim3(3072 / 128, MROWS / 128), blk, GEMM_SMEM_BYTES>>>(
        xh, wph, nullptr, nullptr, qkvh, 3072, DMODEL, 0);

    // attention -> uh fp16
    attn_reg<<<dim3(SEQ / BQ, 64), blk, ATTN_SMEM>>>(qkvh, maskh, uh);

    // xh + u @ Wc^T -> t1h;  LN1 -> t2h (fp16 only)
    gemm_h<<<dim3(DMODEL / 128, MROWS / 128), blk, GEMM_SMEM_BYTES>>>(
        uh, wch, nullptr, xh, t1h, DMODEL, DMODEL, 3);
    ln_h<<<MROWS, blk>>>(t1h, g1, be1, nullptr, t2h);

    // FFN: relu(t2h@W1^T+b1) -> hidh;  hid@W2^T+b2 + t2h -> t3h;  LN2 -> out
    gemm_h<<<dim3(FFDIM / 128, MROWS / 128), blk, GEMM_SMEM_BYTES>>>(
        t2h, w1h, b1, nullptr, hidh, FFDIM, DMODEL, 1);
    gemm_h<<<dim3(DMODEL / 128, MROWS / 128), blk, GEMM_SMEM_BYTES>>>(
        hidh, w2h, b2, t2h, t3h, DMODEL, FFDIM, 2);
    ln_h<<<MROWS, blk>>>(t3h, g2, be2, out, nullptr);
}